// round 2
// baseline (speedup 1.0000x reference)
#include <cuda_runtime.h>
#include <math.h>

// ---------------------------------------------------------------------------
// Static device scratch (allocation-free per harness rules)
// ---------------------------------------------------------------------------
__device__ float g_r [4*1024*1024];
__device__ float g_d [4*1024*1024];
__device__ float g_l [4*1024*1024];
__device__ float g_Q [4*1024*1024];
__device__ float g_K [4*1024*1024];
__device__ float g_V [4*1024*1024];
__device__ float g_S [4*8*128*128];
__device__ float g_AV[4*1024*1024];
__device__ float g_cr[4*1024*1024];
__device__ float g_cd[4*1024*1024];
__device__ float g_cl[4*1024*1024];
__device__ float g_pool[3*4*1024];
__device__ float g_hid [3*4*64];
__device__ float g_seg [3*4*1024];
__device__ float g_qual[3*4*1024];   // [0]=rgb_var [4096]=depth_sp [8192]=lidar_sp
__device__ float g_gates[4*3*1024];
__device__ float g_fused[4*3072*1024];

// ---------------------------------------------------------------------------
// Generic batched SGEMM: C[z] = A[z] (MxK, row-major) * B[z] (KxN, row-major)
//   (+ bias[m]) (+= existing C if accum). Block tile 128x128, K-tile 8,
//   256 threads, 8x8 per thread. All dims here are multiples of the tiles.
// ---------------------------------------------------------------------------
__global__ __launch_bounds__(256, 2) void sgemm(
    const float* __restrict__ A, long long sA,
    const float* __restrict__ Bm, long long sB,
    float* __restrict__ Cm, long long sC,
    const float* __restrict__ bias,
    int M, int N, int K, int accum)
{
    __shared__ float As[8][128];
    __shared__ float Bs[8][128];
    const float* Ab = A  + (long long)blockIdx.z * sA;
    const float* Bb = Bm + (long long)blockIdx.z * sB;
    float*       Cb = Cm + (long long)blockIdx.z * sC;
    const int brow = blockIdx.y << 7;
    const int bcol = blockIdx.x << 7;
    const int tid = threadIdx.x;
    const int ty = tid >> 4, tx = tid & 15;

    float acc[8][8];
#pragma unroll
    for (int i = 0; i < 8; i++)
#pragma unroll
        for (int j = 0; j < 8; j++) acc[i][j] = 0.f;

    const int arow = tid >> 1;
    const int acol = (tid & 1) << 2;
    const int brw  = tid >> 5;
    const int bcl  = (tid & 31) << 2;
    const float* Ap = Ab + (long long)(brow + arow) * K + acol;
    const float* Bp = Bb + (long long)brw * N + bcol + bcl;

    for (int k0 = 0; k0 < K; k0 += 8) {
        float4 av = *(const float4*)(Ap + k0);
        As[acol + 0][arow] = av.x;
        As[acol + 1][arow] = av.y;
        As[acol + 2][arow] = av.z;
        As[acol + 3][arow] = av.w;
        float4 bv = *(const float4*)(Bp + (long long)k0 * N);
        *(float4*)&Bs[brw][bcl] = bv;
        __syncthreads();
#pragma unroll
        for (int kk = 0; kk < 8; kk++) {
            float a[8], b[8];
#pragma unroll
            for (int i = 0; i < 8; i++) a[i] = As[kk][(ty << 3) + i];
#pragma unroll
            for (int j = 0; j < 8; j++) b[j] = Bs[kk][(tx << 3) + j];
#pragma unroll
            for (int i = 0; i < 8; i++)
#pragma unroll
                for (int j = 0; j < 8; j++) acc[i][j] = fmaf(a[i], b[j], acc[i][j]);
        }
        __syncthreads();
    }
#pragma unroll
    for (int i = 0; i < 8; i++) {
        int row = brow + (ty << 3) + i;
        float bsv = bias ? bias[row] : 0.f;
        float* Cp = Cb + (long long)row * N + bcol + (tx << 3);
#pragma unroll
        for (int j = 0; j < 8; j += 4) {
            float4 v;
            v.x = acc[i][j + 0] + bsv;
            v.y = acc[i][j + 1] + bsv;
            v.z = acc[i][j + 2] + bsv;
            v.w = acc[i][j + 3] + bsv;
            if (accum) {
                float4 o = *(const float4*)(Cp + j);
                v.x += o.x; v.y += o.y; v.z += o.z; v.w += o.w;
            }
            *(float4*)(Cp + j) = v;
        }
    }
}

// ---------------------------------------------------------------------------
// Scores: S[z][h][k] = scale * sum_p Q[z*128+h][p] * K[z*128+k][p]
// z in [0,32) = b*8+n. 64x64 output tiles -> 128 blocks for occupancy.
// ---------------------------------------------------------------------------
__global__ __launch_bounds__(256) void scoresk(
    const float* __restrict__ Qm, const float* __restrict__ Km,
    float* __restrict__ S)
{
    __shared__ float Qs[16][64];
    __shared__ float Ks[16][64];
    const int z  = blockIdx.x;
    const int th = blockIdx.y >> 1, tw = blockIdx.y & 1;
    const float* Qb = Qm + (long long)z * 131072 + (long long)th * 65536;
    const float* Kb = Km + (long long)z * 131072 + (long long)tw * 65536;
    const int tid = threadIdx.x;
    const int ty = tid >> 4, tx = tid & 15;
    float acc[4][4];
#pragma unroll
    for (int i = 0; i < 4; i++)
#pragma unroll
        for (int j = 0; j < 4; j++) acc[i][j] = 0.f;
    const int lr = tid >> 2;
    const int lc = (tid & 3) << 2;
    for (int k0 = 0; k0 < 1024; k0 += 16) {
        float4 q = *(const float4*)(Qb + (long long)lr * 1024 + k0 + lc);
        Qs[lc + 0][lr] = q.x; Qs[lc + 1][lr] = q.y;
        Qs[lc + 2][lr] = q.z; Qs[lc + 3][lr] = q.w;
        float4 k = *(const float4*)(Kb + (long long)lr * 1024 + k0 + lc);
        Ks[lc + 0][lr] = k.x; Ks[lc + 1][lr] = k.y;
        Ks[lc + 2][lr] = k.z; Ks[lc + 3][lr] = k.w;
        __syncthreads();
#pragma unroll
        for (int kk = 0; kk < 16; kk++) {
            float a[4], b[4];
#pragma unroll
            for (int i = 0; i < 4; i++) a[i] = Qs[kk][(ty << 2) + i];
#pragma unroll
            for (int j = 0; j < 4; j++) b[j] = Ks[kk][(tx << 2) + j];
#pragma unroll
            for (int i = 0; i < 4; i++)
#pragma unroll
                for (int j = 0; j < 4; j++) acc[i][j] = fmaf(a[i], b[j], acc[i][j]);
        }
        __syncthreads();
    }
    const float scale = 0.08838834764831845f; // 128^-0.5
#pragma unroll
    for (int i = 0; i < 4; i++)
#pragma unroll
        for (int j = 0; j < 4; j++)
            S[(long long)z * 16384 + (th * 64 + (ty << 2) + i) * 128
              + tw * 64 + (tx << 2) + j] = acc[i][j] * scale;
}

// ---------------------------------------------------------------------------
// Softmax over 128-length rows. grid = 4096 rows, 128 threads.
// ---------------------------------------------------------------------------
__global__ void softmaxk(float* __restrict__ S)
{
    float* row = S + (long long)blockIdx.x * 128;
    const int t = threadIdx.x;
    const int lane = t & 31, w = t >> 5;
    __shared__ float sh[4];
    float v = row[t];
    float m = v;
#pragma unroll
    for (int o = 16; o; o >>= 1) m = fmaxf(m, __shfl_xor_sync(~0u, m, o));
    if (!lane) sh[w] = m;
    __syncthreads();
    m = fmaxf(fmaxf(sh[0], sh[1]), fmaxf(sh[2], sh[3]));
    float e = expf(v - m);
    float s = e;
#pragma unroll
    for (int o = 16; o; o >>= 1) s += __shfl_xor_sync(~0u, s, o);
    __syncthreads();
    if (!lane) sh[w] = s;
    __syncthreads();
    s = sh[0] + sh[1] + sh[2] + sh[3];
    row[t] = e / s;
}

// ---------------------------------------------------------------------------
// In-place L2 norm over channel dim (stride 1024) per (b, pixel).
// grid (4, 32), block (32, 8).
// ---------------------------------------------------------------------------
__global__ void l2normk(float* __restrict__ X)
{
    const int b = blockIdx.x;
    const int tx = threadIdx.x, ty = threadIdx.y;
    const int p = blockIdx.y * 32 + tx;
    float* Xb = X + (long long)b * 1048576;
    float s = 0.f;
    for (int r = ty; r < 1024; r += 8) {
        float v = Xb[(long long)r * 1024 + p];
        s += v * v;
    }
    __shared__ float red[8][32];
    red[ty][tx] = s;
    __syncthreads();
    if (ty == 0) {
        float t = 0.f;
#pragma unroll
        for (int i = 0; i < 8; i++) t += red[i][tx];
        red[0][tx] = 1.f / fmaxf(sqrtf(t), 1e-12f);
    }
    __syncthreads();
    const float inv = red[0][tx];
    for (int r = ty; r < 1024; r += 8)
        Xb[(long long)r * 1024 + p] *= inv;
}

// ---------------------------------------------------------------------------
// Column stats: mode 0 -> unbiased variance, mode 1 -> exact-zero fraction.
// grid (4, 32), block (32, 8). out[b*1024 + p].
// ---------------------------------------------------------------------------
__global__ void colstatk(const float* __restrict__ X, float* __restrict__ out, int mode)
{
    const int b = blockIdx.x;
    const int tx = threadIdx.x, ty = threadIdx.y;
    const int p = blockIdx.y * 32 + tx;
    const float* Xb = X + (long long)b * 1048576;
    float s1 = 0.f, s2 = 0.f;
    for (int r = ty; r < 1024; r += 8) {
        float v = Xb[(long long)r * 1024 + p];
        if (mode == 0) { s1 += v; s2 += v * v; }
        else           { s1 += (v == 0.f) ? 1.f : 0.f; }
    }
    __shared__ float r1[8][32], r2[8][32];
    r1[ty][tx] = s1; r2[ty][tx] = s2;
    __syncthreads();
    if (ty == 0) {
        float a = 0.f, c2 = 0.f;
#pragma unroll
        for (int i = 0; i < 8; i++) { a += r1[i][tx]; c2 += r2[i][tx]; }
        float res = (mode == 0) ? (c2 - a * a * (1.f / 1024.f)) * (1.f / 1023.f)
                                : a * (1.f / 1024.f);
        out[b * 1024 + p] = res;
    }
}

// cross = base-feature init (3 buffers at once), float4 elements
__global__ void copy3k(const float4* __restrict__ r, const float4* __restrict__ d,
                       const float4* __restrict__ l, float4* __restrict__ cr,
                       float4* __restrict__ cd, float4* __restrict__ cl)
{
    const int i = blockIdx.x * 256 + threadIdx.x;
    cr[i] = r[i]; cd[i] = d[i]; cl[i] = l[i];
}

// Row mean over the 1024 spatial positions; one warp per row, 8 rows/block.
__global__ void poolk(const float* __restrict__ X, float* __restrict__ out)
{
    const int row = blockIdx.x * 8 + (threadIdx.x >> 5);
    const int lane = threadIdx.x & 31;
    const float* Xr = X + (long long)row * 1024;
    float s = 0.f;
    for (int i = lane; i < 1024; i += 32) s += Xr[i];
#pragma unroll
    for (int o = 16; o; o >>= 1) s += __shfl_xor_sync(~0u, s, o);
    if (!lane) out[row] = s * (1.f / 1024.f);
}

// SE hidden: h = relu(W1 @ pooled + b1). grid (4 batch, 3 modality), 64 thr.
__global__ void se1k(const float* __restrict__ w1, const float* __restrict__ b1,
                     const float* __restrict__ pool, float* __restrict__ hid)
{
    const int b = blockIdx.x, m = blockIdx.y, o = threadIdx.x;
    const float4* w = (const float4*)(w1 + ((long long)m * 64 + o) * 1024);
    const float4* p = (const float4*)(pool + (m * 4 + b) * 1024);
    float s = b1[m * 64 + o];
    for (int c = 0; c < 256; c++) {
        float4 a = w[c], q = p[c];
        s += a.x * q.x + a.y * q.y + a.z * q.z + a.w * q.w;
    }
    hid[(m * 4 + b) * 64 + o] = fmaxf(s, 0.f);
}

// SE gate: g = sigmoid(W2 @ h + b2). grid (4, 3), 256 thr.
__global__ void se2k(const float* __restrict__ w2, const float* __restrict__ b2,
                     const float* __restrict__ hid, float* __restrict__ seg)
{
    const int b = blockIdx.x, m = blockIdx.y;
    const float4* h4 = (const float4*)(hid + (m * 4 + b) * 64);
    for (int o = threadIdx.x; o < 1024; o += 256) {
        const float4* w = (const float4*)(w2 + ((long long)m * 1024 + o) * 64);
        float s = b2[m * 1024 + o];
#pragma unroll
        for (int c = 0; c < 16; c++) {
            float4 a = w[c], q = h4[c];
            s += a.x * q.x + a.y * q.y + a.z * q.z + a.w * q.w;
        }
        seg[(m * 4 + b) * 1024 + o] = 1.f / (1.f + expf(-s));
    }
}

// ref = cross * se_gate (broadcast over spatial). 1M float4 per modality.
__global__ void sescalek(float4* __restrict__ cr, float4* __restrict__ cd,
                         float4* __restrict__ cl, const float* __restrict__ seg)
{
    const int i = blockIdx.x * 256 + threadIdx.x;   // [0, 1048576)
    const int b = i >> 18;
    const int c = (i >> 8) & 1023;
    float4 v;
    float g0 = seg[b * 1024 + c];
    v = cr[i]; v.x *= g0; v.y *= g0; v.z *= g0; v.w *= g0; cr[i] = v;
    float g1 = seg[(4 + b) * 1024 + c];
    v = cd[i]; v.x *= g1; v.y *= g1; v.z *= g1; v.w *= g1; cd[i] = v;
    float g2 = seg[(8 + b) * 1024 + c];
    v = cl[i]; v.x *= g2; v.y *= g2; v.z *= g2; v.w *= g2; cl[i] = v;
}

// gates[b][j][p] = sigmoid(gate_w[j] . combined[:,p] + gate_b[j])
__global__ void gatek(const float* __restrict__ cr, const float* __restrict__ cd,
                      const float* __restrict__ cl, const float* __restrict__ gw,
                      const float* __restrict__ gb, const float* __restrict__ qual,
                      float* __restrict__ gates)
{
    const int b = blockIdx.x;
    const int tx = threadIdx.x, ty = threadIdx.y;
    const int p = blockIdx.y * 32 + tx;
    float a0 = 0.f, a1 = 0.f, a2 = 0.f;
#pragma unroll
    for (int m = 0; m < 3; m++) {
        const float* Xb = (m == 0 ? cr : m == 1 ? cd : cl) + (long long)b * 1048576;
        const float* w0 = gw + m * 1024;
        for (int r = ty; r < 1024; r += 8) {
            float v = Xb[(long long)r * 1024 + p];
            a0 += w0[r] * v;
            a1 += w0[3075 + r] * v;
            a2 += w0[6150 + r] * v;
        }
    }
    __shared__ float red[3][8][32];
    red[0][ty][tx] = a0; red[1][ty][tx] = a1; red[2][ty][tx] = a2;
    __syncthreads();
    if (ty < 3) {
        float s = 0.f;
#pragma unroll
        for (int i = 0; i < 8; i++) s += red[ty][i][tx];
        float var = qual[b * 1024 + p];
        float spd = qual[4096 + b * 1024 + p];
        float spl = qual[8192 + b * 1024 + p];
        const float* wj = gw + ty * 3075;
        s += wj[3072] * var + wj[3073] * spd + wj[3074] * spl + gb[ty];
        gates[(b * 3 + ty) * 1024 + p] = 1.f / (1.f + expf(-s));
    }
}

// fused[b][m*1024+c][p] = ref_m[b][c][p] * gates[b][m][p]
__global__ void fusedk(const float4* __restrict__ cr, const float4* __restrict__ cd,
                       const float4* __restrict__ cl, const float* __restrict__ gates,
                       float4* __restrict__ fused)
{
    const int i = blockIdx.x * 256 + threadIdx.x;   // [0, 3145728)
    const int b = i / 786432;
    const int rem = i - b * 786432;
    const int m = rem / 262144;
    const int c = (rem >> 8) & 1023;
    const int p4 = rem & 255;
    const float4* src = (m == 0 ? cr : m == 1 ? cd : cl);
    float4 v = src[b * 262144 + c * 256 + p4];
    float4 g = ((const float4*)gates)[((b * 3 + m) << 8) + p4];
    v.x *= g.x; v.y *= g.y; v.z *= g.z; v.w *= g.w;
    fused[i] = v;
}

// ---------------------------------------------------------------------------
// Host side
// ---------------------------------------------------------------------------
extern "C" void kernel_launch(void* const* d_in, const int* in_sizes, int n_in,
                              void* d_out, int out_size)
{
    const float* rgb        = (const float*)d_in[0];
    const float* depth      = (const float*)d_in[1];
    const float* lidar      = (const float*)d_in[2];
    const float* prw        = (const float*)d_in[3];
    const float* prb        = (const float*)d_in[4];
    const float* pdw        = (const float*)d_in[5];
    const float* pdb        = (const float*)d_in[6];
    const float* plw        = (const float*)d_in[7];
    const float* plb        = (const float*)d_in[8];
    const float* aqw        = (const float*)d_in[9];
    const float* aqb        = (const float*)d_in[10];
    const float* akw        = (const float*)d_in[11];
    const float* akb        = (const float*)d_in[12];
    const float* avw        = (const float*)d_in[13];
    const float* avb        = (const float*)d_in[14];
    const float* aow        = (const float*)d_in[15];
    const float* aob        = (const float*)d_in[16];
    const float* sw1        = (const float*)d_in[17];
    const float* sb1        = (const float*)d_in[18];
    const float* sw2        = (const float*)d_in[19];
    const float* sb2        = (const float*)d_in[20];
    const float* gw         = (const float*)d_in[21];
    const float* gb         = (const float*)d_in[22];
    const float* fw         = (const float*)d_in[23];
    const float* fb         = (const float*)d_in[24];
    float* out              = (float*)d_out;

    float *r, *dd, *ll, *Q, *K, *V, *S, *AV, *cr, *cd, *cl;
    float *pool, *hid, *seg, *qual, *gates, *fused;
    cudaGetSymbolAddress((void**)&r,    g_r);
    cudaGetSymbolAddress((void**)&dd,   g_d);
    cudaGetSymbolAddress((void**)&ll,   g_l);
    cudaGetSymbolAddress((void**)&Q,    g_Q);
    cudaGetSymbolAddress((void**)&K,    g_K);
    cudaGetSymbolAddress((void**)&V,    g_V);
    cudaGetSymbolAddress((void**)&S,    g_S);
    cudaGetSymbolAddress((void**)&AV,   g_AV);
    cudaGetSymbolAddress((void**)&cr,   g_cr);
    cudaGetSymbolAddress((void**)&cd,   g_cd);
    cudaGetSymbolAddress((void**)&cl,   g_cl);
    cudaGetSymbolAddress((void**)&pool, g_pool);
    cudaGetSymbolAddress((void**)&hid,  g_hid);
    cudaGetSymbolAddress((void**)&seg,  g_seg);
    cudaGetSymbolAddress((void**)&qual, g_qual);
    cudaGetSymbolAddress((void**)&gates,g_gates);
    cudaGetSymbolAddress((void**)&fused,g_fused);

    const long long s1M = 1048576LL;

    // 1) projections + L2 norm + quality stats
    sgemm<<<dim3(8, 8, 4), 256>>>(prw, 0, rgb,   512 * 1024LL, r,  s1M, prb, 1024, 1024, 512, 0);
    sgemm<<<dim3(8, 8, 4), 256>>>(pdw, 0, depth, 256 * 1024LL, dd, s1M, pdb, 1024, 1024, 256, 0);
    sgemm<<<dim3(8, 8, 4), 256>>>(plw, 0, lidar,  64 * 1024LL, ll, s1M, plb, 1024, 1024,  64, 0);
    l2normk<<<dim3(4, 32), dim3(32, 8)>>>(r);
    l2normk<<<dim3(4, 32), dim3(32, 8)>>>(dd);
    l2normk<<<dim3(4, 32), dim3(32, 8)>>>(ll);
    colstatk<<<dim3(4, 32), dim3(32, 8)>>>(r,  qual,        0);
    colstatk<<<dim3(4, 32), dim3(32, 8)>>>(dd, qual + 4096, 1);
    colstatk<<<dim3(4, 32), dim3(32, 8)>>>(ll, qual + 8192, 1);
    copy3k<<<4096, 256>>>((const float4*)r, (const float4*)dd, (const float4*)ll,
                          (float4*)cr, (float4*)cd, (float4*)cl);

    // 2) six cross-attention blocks
    const float* qsrc[6]  = { r, r, dd, dd, ll, ll };
    const float* kvsrc[6] = { dd, ll, r, ll, r, dd };
    float*       accb[6]  = { cr, cr, cd, cd, cl, cl };
    for (int i = 0; i < 6; i++) {
        const long long wo = (long long)i * 1048576;
        sgemm<<<dim3(8, 8, 4), 256>>>(aqw + wo, 0, qsrc[i],  s1M, Q, s1M, aqb + i * 1024, 1024, 1024, 1024, 0);
        sgemm<<<dim3(8, 8, 4), 256>>>(akw + wo, 0, kvsrc[i], s1M, K, s1M, akb + i * 1024, 1024, 1024, 1024, 0);
        sgemm<<<dim3(8, 8, 4), 256>>>(avw + wo, 0, kvsrc[i], s1M, V, s1M, avb + i * 1024, 1024, 1024, 1024, 0);
        scoresk<<<dim3(32, 4), 256>>>(Q, K, S);
        softmaxk<<<4096, 128>>>(S);
        sgemm<<<dim3(8, 1, 32), 256>>>(S, 16384, V, 131072, AV, 131072, (const float*)0, 128, 1024, 128, 0);
        sgemm<<<dim3(8, 8, 4), 256>>>(aow + wo, 0, AV, s1M, accb[i], s1M, aob + i * 1024, 1024, 1024, 1024, 1);
    }

    // 3) SE gating
    poolk<<<512, 256>>>(cr, pool);
    poolk<<<512, 256>>>(cd, pool + 4096);
    poolk<<<512, 256>>>(cl, pool + 8192);
    se1k<<<dim3(4, 3), 64>>>(sw1, sb1, pool, hid);
    se2k<<<dim3(4, 3), 256>>>(sw2, sb2, hid, seg);
    sescalek<<<4096, 256>>>((float4*)cr, (float4*)cd, (float4*)cl, seg);

    // 4) adaptive gates + gated concat
    gatek<<<dim3(4, 32), dim3(32, 8)>>>(cr, cd, cl, gw, gb, qual, gates);
    fusedk<<<12288, 256>>>((const float4*)cr, (const float4*)cd, (const float4*)cl,
                           gates, (float4*)fused);

    // 5) final fusion conv (3072x3072) straight into d_out
    sgemm<<<dim3(8, 24, 4), 256>>>(fw, 0, fused, 3072 * 1024LL, out, 3072 * 1024LL,
                                   fb, 3072, 1024, 3072, 0);
}

// round 3
// speedup vs baseline: 1.0017x; 1.0017x over previous
#include <cuda_runtime.h>
#include <math.h>

// ---------------------------------------------------------------------------
// Static device scratch (allocation-free per harness rules)
// ---------------------------------------------------------------------------
__device__ float g_r [4*1024*1024];
__device__ float g_d [4*1024*1024];
__device__ float g_l [4*1024*1024];
__device__ float g_Q [4*1024*1024];
__device__ float g_K [4*1024*1024];
__device__ float g_V [4*1024*1024];
__device__ float g_S [4*8*128*128];
__device__ float g_AV[4*1024*1024];
__device__ float g_cr[4*1024*1024];
__device__ float g_cd[4*1024*1024];
__device__ float g_cl[4*1024*1024];
__device__ float g_pool[3*4*1024];
__device__ float g_hid [3*4*64];
__device__ float g_seg [3*4*1024];
__device__ float g_qual[3*4*1024];   // [0]=rgb_var [4096]=depth_sp [8192]=lidar_sp
__device__ float g_gates[4*3*1024];
__device__ float g_fused[4*3072*1024];

// ---------------------------------------------------------------------------
// Generic batched SGEMM: C[z] = A[z] (MxK, row-major) * B[z] (KxN, row-major)
//   (+ bias[m]) (+= existing C if accum). Block tile 128x128, K-tile 8,
//   256 threads, 8x8 per thread. All dims here are multiples of the tiles.
// ---------------------------------------------------------------------------
__global__ __launch_bounds__(256, 2) void sgemm(
    const float* __restrict__ A, long long sA,
    const float* __restrict__ Bm, long long sB,
    float* __restrict__ Cm, long long sC,
    const float* __restrict__ bias,
    int M, int N, int K, int accum)
{
    __shared__ float As[8][128];
    __shared__ float Bs[8][128];
    const float* Ab = A  + (long long)blockIdx.z * sA;
    const float* Bb = Bm + (long long)blockIdx.z * sB;
    float*       Cb = Cm + (long long)blockIdx.z * sC;
    const int brow = blockIdx.y << 7;
    const int bcol = blockIdx.x << 7;
    const int tid = threadIdx.x;
    const int ty = tid >> 4, tx = tid & 15;

    float acc[8][8];
#pragma unroll
    for (int i = 0; i < 8; i++)
#pragma unroll
        for (int j = 0; j < 8; j++) acc[i][j] = 0.f;

    const int arow = tid >> 1;
    const int acol = (tid & 1) << 2;
    const int brw  = tid >> 5;
    const int bcl  = (tid & 31) << 2;
    const float* Ap = Ab + (long long)(brow + arow) * K + acol;
    const float* Bp = Bb + (long long)brw * N + bcol + bcl;

    for (int k0 = 0; k0 < K; k0 += 8) {
        float4 av = *(const float4*)(Ap + k0);
        As[acol + 0][arow] = av.x;
        As[acol + 1][arow] = av.y;
        As[acol + 2][arow] = av.z;
        As[acol + 3][arow] = av.w;
        float4 bv = *(const float4*)(Bp + (long long)k0 * N);
        *(float4*)&Bs[brw][bcl] = bv;
        __syncthreads();
#pragma unroll
        for (int kk = 0; kk < 8; kk++) {
            float a[8], b[8];
#pragma unroll
            for (int i = 0; i < 8; i++) a[i] = As[kk][(ty << 3) + i];
#pragma unroll
            for (int j = 0; j < 8; j++) b[j] = Bs[kk][(tx << 3) + j];
#pragma unroll
            for (int i = 0; i < 8; i++)
#pragma unroll
                for (int j = 0; j < 8; j++) acc[i][j] = fmaf(a[i], b[j], acc[i][j]);
        }
        __syncthreads();
    }
#pragma unroll
    for (int i = 0; i < 8; i++) {
        int row = brow + (ty << 3) + i;
        float bsv = bias ? bias[row] : 0.f;
        float* Cp = Cb + (long long)row * N + bcol + (tx << 3);
#pragma unroll
        for (int j = 0; j < 8; j += 4) {
            float4 v;
            v.x = acc[i][j + 0] + bsv;
            v.y = acc[i][j + 1] + bsv;
            v.z = acc[i][j + 2] + bsv;
            v.w = acc[i][j + 3] + bsv;
            if (accum) {
                float4 o = *(const float4*)(Cp + j);
                v.x += o.x; v.y += o.y; v.z += o.z; v.w += o.w;
            }
            *(float4*)(Cp + j) = v;
        }
    }
}

// ---------------------------------------------------------------------------
// Scores: S[z][h][k] = scale * sum_p Q[z*128+h][p] * K[z*128+k][p]
// z in [0,32) = b*8+n. 64x64 output tiles -> 128 blocks for occupancy.
// ---------------------------------------------------------------------------
__global__ __launch_bounds__(256) void scoresk(
    const float* __restrict__ Qm, const float* __restrict__ Km,
    float* __restrict__ S)
{
    __shared__ float Qs[16][64];
    __shared__ float Ks[16][64];
    const int z  = blockIdx.x;
    const int th = blockIdx.y >> 1, tw = blockIdx.y & 1;
    const float* Qb = Qm + (long long)z * 131072 + (long long)th * 65536;
    const float* Kb = Km + (long long)z * 131072 + (long long)tw * 65536;
    const int tid = threadIdx.x;
    const int ty = tid >> 4, tx = tid & 15;
    float acc[4][4];
#pragma unroll
    for (int i = 0; i < 4; i++)
#pragma unroll
        for (int j = 0; j < 4; j++) acc[i][j] = 0.f;
    const int lr = tid >> 2;
    const int lc = (tid & 3) << 2;
    for (int k0 = 0; k0 < 1024; k0 += 16) {
        float4 q = *(const float4*)(Qb + (long long)lr * 1024 + k0 + lc);
        Qs[lc + 0][lr] = q.x; Qs[lc + 1][lr] = q.y;
        Qs[lc + 2][lr] = q.z; Qs[lc + 3][lr] = q.w;
        float4 k = *(const float4*)(Kb + (long long)lr * 1024 + k0 + lc);
        Ks[lc + 0][lr] = k.x; Ks[lc + 1][lr] = k.y;
        Ks[lc + 2][lr] = k.z; Ks[lc + 3][lr] = k.w;
        __syncthreads();
#pragma unroll
        for (int kk = 0; kk < 16; kk++) {
            float a[4], b[4];
#pragma unroll
            for (int i = 0; i < 4; i++) a[i] = Qs[kk][(ty << 2) + i];
#pragma unroll
            for (int j = 0; j < 4; j++) b[j] = Ks[kk][(tx << 2) + j];
#pragma unroll
            for (int i = 0; i < 4; i++)
#pragma unroll
                for (int j = 0; j < 4; j++) acc[i][j] = fmaf(a[i], b[j], acc[i][j]);
        }
        __syncthreads();
    }
    const float scale = 0.08838834764831845f; // 128^-0.5
#pragma unroll
    for (int i = 0; i < 4; i++)
#pragma unroll
        for (int j = 0; j < 4; j++)
            S[(long long)z * 16384 + (th * 64 + (ty << 2) + i) * 128
              + tw * 64 + (tx << 2) + j] = acc[i][j] * scale;
}

// ---------------------------------------------------------------------------
// Softmax over 128-length rows. grid = 4096 rows, 128 threads.
// ---------------------------------------------------------------------------
__global__ void softmaxk(float* __restrict__ S)
{
    float* row = S + (long long)blockIdx.x * 128;
    const int t = threadIdx.x;
    const int lane = t & 31, w = t >> 5;
    __shared__ float sh[4];
    float v = row[t];
    float m = v;
#pragma unroll
    for (int o = 16; o; o >>= 1) m = fmaxf(m, __shfl_xor_sync(~0u, m, o));
    if (!lane) sh[w] = m;
    __syncthreads();
    m = fmaxf(fmaxf(sh[0], sh[1]), fmaxf(sh[2], sh[3]));
    float e = expf(v - m);
    float s = e;
#pragma unroll
    for (int o = 16; o; o >>= 1) s += __shfl_xor_sync(~0u, s, o);
    __syncthreads();
    if (!lane) sh[w] = s;
    __syncthreads();
    s = sh[0] + sh[1] + sh[2] + sh[3];
    row[t] = e / s;
}

// ---------------------------------------------------------------------------
// In-place L2 norm over channel dim (stride 1024) per (b, pixel).
// grid (4, 32), block (32, 8).
// ---------------------------------------------------------------------------
__global__ void l2normk(float* __restrict__ X)
{
    const int b = blockIdx.x;
    const int tx = threadIdx.x, ty = threadIdx.y;
    const int p = blockIdx.y * 32 + tx;
    float* Xb = X + (long long)b * 1048576;
    float s = 0.f;
    for (int r = ty; r < 1024; r += 8) {
        float v = Xb[(long long)r * 1024 + p];
        s += v * v;
    }
    __shared__ float red[8][32];
    red[ty][tx] = s;
    __syncthreads();
    if (ty == 0) {
        float t = 0.f;
#pragma unroll
        for (int i = 0; i < 8; i++) t += red[i][tx];
        red[0][tx] = 1.f / fmaxf(sqrtf(t), 1e-12f);
    }
    __syncthreads();
    const float inv = red[0][tx];
    for (int r = ty; r < 1024; r += 8)
        Xb[(long long)r * 1024 + p] *= inv;
}

// ---------------------------------------------------------------------------
// Column stats: mode 0 -> unbiased variance, mode 1 -> exact-zero fraction.
// grid (4, 32), block (32, 8). out[b*1024 + p].
// ---------------------------------------------------------------------------
__global__ void colstatk(const float* __restrict__ X, float* __restrict__ out, int mode)
{
    const int b = blockIdx.x;
    const int tx = threadIdx.x, ty = threadIdx.y;
    const int p = blockIdx.y * 32 + tx;
    const float* Xb = X + (long long)b * 1048576;
    float s1 = 0.f, s2 = 0.f;
    for (int r = ty; r < 1024; r += 8) {
        float v = Xb[(long long)r * 1024 + p];
        if (mode == 0) { s1 += v; s2 += v * v; }
        else           { s1 += (v == 0.f) ? 1.f : 0.f; }
    }
    __shared__ float r1[8][32], r2[8][32];
    r1[ty][tx] = s1; r2[ty][tx] = s2;
    __syncthreads();
    if (ty == 0) {
        float a = 0.f, c2 = 0.f;
#pragma unroll
        for (int i = 0; i < 8; i++) { a += r1[i][tx]; c2 += r2[i][tx]; }
        float res = (mode == 0) ? (c2 - a * a * (1.f / 1024.f)) * (1.f / 1023.f)
                                : a * (1.f / 1024.f);
        out[b * 1024 + p] = res;
    }
}

// cross = base-feature init (3 buffers at once), float4 elements
__global__ void copy3k(const float4* __restrict__ r, const float4* __restrict__ d,
                       const float4* __restrict__ l, float4* __restrict__ cr,
                       float4* __restrict__ cd, float4* __restrict__ cl)
{
    const int i = blockIdx.x * 256 + threadIdx.x;
    cr[i] = r[i]; cd[i] = d[i]; cl[i] = l[i];
}

// Row mean over the 1024 spatial positions; one warp per row, 8 rows/block.
__global__ void poolk(const float* __restrict__ X, float* __restrict__ out)
{
    const int row = blockIdx.x * 8 + (threadIdx.x >> 5);
    const int lane = threadIdx.x & 31;
    const float* Xr = X + (long long)row * 1024;
    float s = 0.f;
    for (int i = lane; i < 1024; i += 32) s += Xr[i];
#pragma unroll
    for (int o = 16; o; o >>= 1) s += __shfl_xor_sync(~0u, s, o);
    if (!lane) out[row] = s * (1.f / 1024.f);
}

// SE hidden: h = relu(W1 @ pooled + b1). grid (4 batch, 3 modality), 64 thr.
__global__ void se1k(const float* __restrict__ w1, const float* __restrict__ b1,
                     const float* __restrict__ pool, float* __restrict__ hid)
{
    const int b = blockIdx.x, m = blockIdx.y, o = threadIdx.x;
    const float4* w = (const float4*)(w1 + ((long long)m * 64 + o) * 1024);
    const float4* p = (const float4*)(pool + (m * 4 + b) * 1024);
    float s = b1[m * 64 + o];
    for (int c = 0; c < 256; c++) {
        float4 a = w[c], q = p[c];
        s += a.x * q.x + a.y * q.y + a.z * q.z + a.w * q.w;
    }
    hid[(m * 4 + b) * 64 + o] = fmaxf(s, 0.f);
}

// SE gate: g = sigmoid(W2 @ h + b2). grid (4, 3), 256 thr.
__global__ void se2k(const float* __restrict__ w2, const float* __restrict__ b2,
                     const float* __restrict__ hid, float* __restrict__ seg)
{
    const int b = blockIdx.x, m = blockIdx.y;
    const float4* h4 = (const float4*)(hid + (m * 4 + b) * 64);
    for (int o = threadIdx.x; o < 1024; o += 256) {
        const float4* w = (const float4*)(w2 + ((long long)m * 1024 + o) * 64);
        float s = b2[m * 1024 + o];
#pragma unroll
        for (int c = 0; c < 16; c++) {
            float4 a = w[c], q = h4[c];
            s += a.x * q.x + a.y * q.y + a.z * q.z + a.w * q.w;
        }
        seg[(m * 4 + b) * 1024 + o] = 1.f / (1.f + expf(-s));
    }
}

// ref = cross * se_gate (broadcast over spatial). 1M float4 per modality.
__global__ void sescalek(float4* __restrict__ cr, float4* __restrict__ cd,
                         float4* __restrict__ cl, const float* __restrict__ seg)
{
    const int i = blockIdx.x * 256 + threadIdx.x;   // [0, 1048576)
    const int b = i >> 18;
    const int c = (i >> 8) & 1023;
    float4 v;
    float g0 = seg[b * 1024 + c];
    v = cr[i]; v.x *= g0; v.y *= g0; v.z *= g0; v.w *= g0; cr[i] = v;
    float g1 = seg[(4 + b) * 1024 + c];
    v = cd[i]; v.x *= g1; v.y *= g1; v.z *= g1; v.w *= g1; cd[i] = v;
    float g2 = seg[(8 + b) * 1024 + c];
    v = cl[i]; v.x *= g2; v.y *= g2; v.z *= g2; v.w *= g2; cl[i] = v;
}

// gates[b][j][p] = sigmoid(gate_w[j] . combined[:,p] + gate_b[j])
__global__ void gatek(const float* __restrict__ cr, const float* __restrict__ cd,
                      const float* __restrict__ cl, const float* __restrict__ gw,
                      const float* __restrict__ gb, const float* __restrict__ qual,
                      float* __restrict__ gates)
{
    const int b = blockIdx.x;
    const int tx = threadIdx.x, ty = threadIdx.y;
    const int p = blockIdx.y * 32 + tx;
    float a0 = 0.f, a1 = 0.f, a2 = 0.f;
#pragma unroll
    for (int m = 0; m < 3; m++) {
        const float* Xb = (m == 0 ? cr : m == 1 ? cd : cl) + (long long)b * 1048576;
        const float* w0 = gw + m * 1024;
        for (int r = ty; r < 1024; r += 8) {
            float v = Xb[(long long)r * 1024 + p];
            a0 += w0[r] * v;
            a1 += w0[3075 + r] * v;
            a2 += w0[6150 + r] * v;
        }
    }
    __shared__ float red[3][8][32];
    red[0][ty][tx] = a0; red[1][ty][tx] = a1; red[2][ty][tx] = a2;
    __syncthreads();
    if (ty < 3) {
        float s = 0.f;
#pragma unroll
        for (int i = 0; i < 8; i++) s += red[ty][i][tx];
        float var = qual[b * 1024 + p];
        float spd = qual[4096 + b * 1024 + p];
        float spl = qual[8192 + b * 1024 + p];
        const float* wj = gw + ty * 3075;
        s += wj[3072] * var + wj[3073] * spd + wj[3074] * spl + gb[ty];
        gates[(b * 3 + ty) * 1024 + p] = 1.f / (1.f + expf(-s));
    }
}

// fused[b][m*1024+c][p] = ref_m[b][c][p] * gates[b][m][p]
__global__ void fusedk(const float4* __restrict__ cr, const float4* __restrict__ cd,
                       const float4* __restrict__ cl, const float* __restrict__ gates,
                       float4* __restrict__ fused)
{
    const int i = blockIdx.x * 256 + threadIdx.x;   // [0, 3145728)
    const int b = i / 786432;
    const int rem = i - b * 786432;
    const int m = rem / 262144;
    const int c = (rem >> 8) & 1023;
    const int p4 = rem & 255;
    const float4* src = (m == 0 ? cr : m == 1 ? cd : cl);
    float4 v = src[b * 262144 + c * 256 + p4];
    float4 g = ((const float4*)gates)[((b * 3 + m) << 8) + p4];
    v.x *= g.x; v.y *= g.y; v.z *= g.z; v.w *= g.w;
    fused[i] = v;
}

// ---------------------------------------------------------------------------
// Host side
// ---------------------------------------------------------------------------
extern "C" void kernel_launch(void* const* d_in, const int* in_sizes, int n_in,
                              void* d_out, int out_size)
{
    const float* rgb        = (const float*)d_in[0];
    const float* depth      = (const float*)d_in[1];
    const float* lidar      = (const float*)d_in[2];
    const float* prw        = (const float*)d_in[3];
    const float* prb        = (const float*)d_in[4];
    const float* pdw        = (const float*)d_in[5];
    const float* pdb        = (const float*)d_in[6];
    const float* plw        = (const float*)d_in[7];
    const float* plb        = (const float*)d_in[8];
    const float* aqw        = (const float*)d_in[9];
    const float* aqb        = (const float*)d_in[10];
    const float* akw        = (const float*)d_in[11];
    const float* akb        = (const float*)d_in[12];
    const float* avw        = (const float*)d_in[13];
    const float* avb        = (const float*)d_in[14];
    const float* aow        = (const float*)d_in[15];
    const float* aob        = (const float*)d_in[16];
    const float* sw1        = (const float*)d_in[17];
    const float* sb1        = (const float*)d_in[18];
    const float* sw2        = (const float*)d_in[19];
    const float* sb2        = (const float*)d_in[20];
    const float* gw         = (const float*)d_in[21];
    const float* gb         = (const float*)d_in[22];
    const float* fw         = (const float*)d_in[23];
    const float* fb         = (const float*)d_in[24];
    float* out              = (float*)d_out;

    float *r, *dd, *ll, *Q, *K, *V, *S, *AV, *cr, *cd, *cl;
    float *pool, *hid, *seg, *qual, *gates, *fused;
    cudaGetSymbolAddress((void**)&r,    g_r);
    cudaGetSymbolAddress((void**)&dd,   g_d);
    cudaGetSymbolAddress((void**)&ll,   g_l);
    cudaGetSymbolAddress((void**)&Q,    g_Q);
    cudaGetSymbolAddress((void**)&K,    g_K);
    cudaGetSymbolAddress((void**)&V,    g_V);
    cudaGetSymbolAddress((void**)&S,    g_S);
    cudaGetSymbolAddress((void**)&AV,   g_AV);
    cudaGetSymbolAddress((void**)&cr,   g_cr);
    cudaGetSymbolAddress((void**)&cd,   g_cd);
    cudaGetSymbolAddress((void**)&cl,   g_cl);
    cudaGetSymbolAddress((void**)&pool, g_pool);
    cudaGetSymbolAddress((void**)&hid,  g_hid);
    cudaGetSymbolAddress((void**)&seg,  g_seg);
    cudaGetSymbolAddress((void**)&qual, g_qual);
    cudaGetSymbolAddress((void**)&gates,g_gates);
    cudaGetSymbolAddress((void**)&fused,g_fused);

    const long long s1M = 1048576LL;

    // 1) projections + L2 norm + quality stats
    sgemm<<<dim3(8, 8, 4), 256>>>(prw, 0, rgb,   512 * 1024LL, r,  s1M, prb, 1024, 1024, 512, 0);
    sgemm<<<dim3(8, 8, 4), 256>>>(pdw, 0, depth, 256 * 1024LL, dd, s1M, pdb, 1024, 1024, 256, 0);
    sgemm<<<dim3(8, 8, 4), 256>>>(plw, 0, lidar,  64 * 1024LL, ll, s1M, plb, 1024, 1024,  64, 0);
    l2normk<<<dim3(4, 32), dim3(32, 8)>>>(r);
    l2normk<<<dim3(4, 32), dim3(32, 8)>>>(dd);
    l2normk<<<dim3(4, 32), dim3(32, 8)>>>(ll);
    colstatk<<<dim3(4, 32), dim3(32, 8)>>>(r,  qual,        0);
    colstatk<<<dim3(4, 32), dim3(32, 8)>>>(dd, qual + 4096, 1);
    colstatk<<<dim3(4, 32), dim3(32, 8)>>>(ll, qual + 8192, 1);
    copy3k<<<4096, 256>>>((const float4*)r, (const float4*)dd, (const float4*)ll,
                          (float4*)cr, (float4*)cd, (float4*)cl);

    // 2) six cross-attention blocks
    const float* qsrc[6]  = { r, r, dd, dd, ll, ll };
    const float* kvsrc[6] = { dd, ll, r, ll, r, dd };
    float*       accb[6]  = { cr, cr, cd, cd, cl, cl };
    for (int i = 0; i < 6; i++) {
        const long long wo = (long long)i * 1048576;
        sgemm<<<dim3(8, 8, 4), 256>>>(aqw + wo, 0, qsrc[i],  s1M, Q, s1M, aqb + i * 1024, 1024, 1024, 1024, 0);
        sgemm<<<dim3(8, 8, 4), 256>>>(akw + wo, 0, kvsrc[i], s1M, K, s1M, akb + i * 1024, 1024, 1024, 1024, 0);
        sgemm<<<dim3(8, 8, 4), 256>>>(avw + wo, 0, kvsrc[i], s1M, V, s1M, avb + i * 1024, 1024, 1024, 1024, 0);
        scoresk<<<dim3(32, 4), 256>>>(Q, K, S);
        softmaxk<<<4096, 128>>>(S);
        sgemm<<<dim3(8, 1, 32), 256>>>(S, 16384, V, 131072, AV, 131072, (const float*)0, 128, 1024, 128, 0);
        sgemm<<<dim3(8, 8, 4), 256>>>(aow + wo, 0, AV, s1M, accb[i], s1M, aob + i * 1024, 1024, 1024, 1024, 1);
    }

    // 3) SE gating
    poolk<<<512, 256>>>(cr, pool);
    poolk<<<512, 256>>>(cd, pool + 4096);
    poolk<<<512, 256>>>(cl, pool + 8192);
    se1k<<<dim3(4, 3), 64>>>(sw1, sb1, pool, hid);
    se2k<<<dim3(4, 3), 256>>>(sw2, sb2, hid, seg);
    sescalek<<<4096, 256>>>((float4*)cr, (float4*)cd, (float4*)cl, seg);

    // 4) adaptive gates + gated concat
    gatek<<<dim3(4, 32), dim3(32, 8)>>>(cr, cd, cl, gw, gb, qual, gates);
    fusedk<<<12288, 256>>>((const float4*)cr, (const float4*)cd, (const float4*)cl,
                           gates, (float4*)fused);

    // 5) final fusion conv (3072x3072) straight into d_out
    sgemm<<<dim3(8, 24, 4), 256>>>(fw, 0, fused, 3072 * 1024LL, out, 3072 * 1024LL,
                                   fb, 3072, 1024, 3072, 0);
}

// round 9
// speedup vs baseline: 1.2185x; 1.2165x over previous
#include <cuda_runtime.h>
#include <cuda_fp16.h>
#include <mma.h>
#include <cstdint>
#include <math.h>

using namespace nvcuda;

// ============================ scratch ======================================
__device__ float g_rt  [4194304];
__device__ float g_dtt [4194304];
__device__ float g_ltt [4194304];
__device__ float g_crt [4194304];
__device__ float g_cdt [4194304];
__device__ float g_clt [4194304];
__device__ float g_Qb  [4194304];
__device__ float g_Kb  [4194304];
__device__ float g_Vb  [4194304];
__device__ float g_Sb  [524288];
__device__ float g_AVt [4194304];
__device__ float g_ft  [12582912];
__device__ float g_pool[12288];
__device__ float g_hid [768];
__device__ float g_seg [12288];
__device__ float g_qual[12288];
__device__ float g_gates[12288];

// ==================== WMMA split-fp16 GEMM =================================
// C[z](m,n) = alpha * sum_k A(m,k)*B(k,n) [+ bias] [+ C_old if flags&1]
// A element (m,k): atrans==0 -> A[m*lda+k], atrans==1 -> A[k*lda+m]
// B element (k,n): btrans==0 -> B[n*ldb+k], btrans==1 -> B[k*ldb+n]
// z offsets: base + (z/div)*so + (z%div)*si for each of A, B, C.
// flags: bit0 accumulate from C, bit1 bias indexed by m (else by n).
// alpha only used when no bias and no accumulate (scores).
static const int LDT = 40;

__global__ __launch_bounds__(256, 2) void tcwmma(
    const float* __restrict__ A, int lda, long long sAo, long long sAi, int adiv, int atrans,
    const float* __restrict__ B, int ldb, long long sBo, long long sBi, int bdiv, int btrans,
    float* __restrict__ C, int ldc, long long sCo, long long sCi, int cdiv,
    const float* __restrict__ bias, float alpha, int flags, int K)
{
    __shared__ __half As_h[128 * LDT];
    __shared__ __half As_l[128 * LDT];
    __shared__ __half Bs_h[128 * LDT];
    __shared__ __half Bs_l[128 * LDT];

    const int tid = threadIdx.x;
    const int wid = tid >> 5;
    const int z = blockIdx.z;
    const int m0 = blockIdx.y << 7, n0 = blockIdx.x << 7;
    const int wm = (wid >> 1) * 32, wn = (wid & 1) * 64;

    const float* Ag = A + (long long)(z / adiv) * sAo + (long long)(z % adiv) * sAi
                        + (atrans ? (long long)m0 : (long long)m0 * lda);
    const float* Bg = B + (long long)(z / bdiv) * sBo + (long long)(z % bdiv) * sBi
                        + (btrans ? (long long)n0 : (long long)n0 * ldb);
    float* Cg = C + (long long)(z / cdiv) * sCo + (long long)(z % cdiv) * sCi
                  + (long long)m0 * ldc + n0;

    wmma::fragment<wmma::accumulator, 16, 16, 16, float> acc[2][4];
#pragma unroll
    for (int i = 0; i < 2; i++)
#pragma unroll
        for (int j = 0; j < 4; j++) {
            if (flags & 1)
                wmma::load_matrix_sync(acc[i][j],
                    Cg + (long long)(wm + i * 16) * ldc + wn + j * 16, ldc,
                    wmma::mem_row_major);
            else
                wmma::fill_fragment(acc[i][j], 0.f);
        }

    // ---- bias as rank-1 MMA over a 16-wide k-step (cols 0,1 = hi,lo) ----
    if (bias) {
        if (tid < 128) {
            const int r = tid;
#pragma unroll
            for (int c = 0; c < 16; c++) {
                As_h[r * LDT + c] = __float2half_rn(0.f);
                Bs_h[r * LDT + c] = __float2half_rn(0.f);
            }
            const __half one = __float2half_rn(1.f);
            if (flags & 2) {           // bias per m
                float bv = bias[m0 + r];
                __half bh = __float2half_rn(bv);
                As_h[r * LDT + 0] = bh;
                As_h[r * LDT + 1] = __float2half_rn(bv - __half2float(bh));
                Bs_h[r * LDT + 0] = one;
                Bs_h[r * LDT + 1] = one;
            } else {                   // bias per n
                float bv = bias[n0 + r];
                __half bh = __float2half_rn(bv);
                Bs_h[r * LDT + 0] = bh;
                Bs_h[r * LDT + 1] = __float2half_rn(bv - __half2float(bh));
                As_h[r * LDT + 0] = one;
                As_h[r * LDT + 1] = one;
            }
        }
        __syncthreads();
        wmma::fragment<wmma::matrix_a, 16, 16, 16, __half, wmma::row_major> af;
        wmma::fragment<wmma::matrix_b, 16, 16, 16, __half, wmma::col_major> bf;
#pragma unroll
        for (int i = 0; i < 2; i++) {
            wmma::load_matrix_sync(af, As_h + (wm + i * 16) * LDT, LDT);
#pragma unroll
            for (int j = 0; j < 4; j++) {
                wmma::load_matrix_sync(bf, Bs_h + (wn + j * 16) * LDT, LDT);
                wmma::mma_sync(acc[i][j], af, bf, acc[i][j]);
            }
        }
        __syncthreads();
    }

    // ---- main loop over K chunks of 32 ----
    const int nc = K >> 5;
    for (int c = 0; c < nc; c++) {
        const int k0 = c << 5;
        // load + fp16-split A
        if (!atrans) {
#pragma unroll
            for (int pass = 0; pass < 4; pass++) {
                const int m = pass * 32 + (tid >> 3);
                const int kq = (tid & 7) * 4;
                float4 v = *(const float4*)(Ag + (long long)m * lda + k0 + kq);
                __half2 h0 = __floats2half2_rn(v.x, v.y), h1 = __floats2half2_rn(v.z, v.w);
                float2 f0 = __half22float2(h0), f1 = __half22float2(h1);
                *(__half2*)&As_h[m * LDT + kq]     = h0;
                *(__half2*)&As_h[m * LDT + kq + 2] = h1;
                *(__half2*)&As_l[m * LDT + kq]     = __floats2half2_rn(v.x - f0.x, v.y - f0.y);
                *(__half2*)&As_l[m * LDT + kq + 2] = __floats2half2_rn(v.z - f1.x, v.w - f1.y);
            }
        } else {
#pragma unroll
            for (int pass = 0; pass < 4; pass++) {
                const int k = pass * 8 + (tid >> 5);
                const int m4 = (tid & 31) * 4;
                float4 v = *(const float4*)(Ag + (long long)(k0 + k) * lda + m4);
                float f[4] = { v.x, v.y, v.z, v.w };
#pragma unroll
                for (int e = 0; e < 4; e++) {
                    __half h = __float2half_rn(f[e]);
                    As_h[(m4 + e) * LDT + k] = h;
                    As_l[(m4 + e) * LDT + k] = __float2half_rn(f[e] - __half2float(h));
                }
            }
        }
        // load + fp16-split B (stored as [n][k] tiles)
        if (!btrans) {
#pragma unroll
            for (int pass = 0; pass < 4; pass++) {
                const int n = pass * 32 + (tid >> 3);
                const int kq = (tid & 7) * 4;
                float4 v = *(const float4*)(Bg + (long long)n * ldb + k0 + kq);
                __half2 h0 = __floats2half2_rn(v.x, v.y), h1 = __floats2half2_rn(v.z, v.w);
                float2 f0 = __half22float2(h0), f1 = __half22float2(h1);
                *(__half2*)&Bs_h[n * LDT + kq]     = h0;
                *(__half2*)&Bs_h[n * LDT + kq + 2] = h1;
                *(__half2*)&Bs_l[n * LDT + kq]     = __floats2half2_rn(v.x - f0.x, v.y - f0.y);
                *(__half2*)&Bs_l[n * LDT + kq + 2] = __floats2half2_rn(v.z - f1.x, v.w - f1.y);
            }
        } else {
#pragma unroll
            for (int pass = 0; pass < 4; pass++) {
                const int k = pass * 8 + (tid >> 5);
                const int n4 = (tid & 31) * 4;
                float4 v = *(const float4*)(Bg + (long long)(k0 + k) * ldb + n4);
                float f[4] = { v.x, v.y, v.z, v.w };
#pragma unroll
                for (int e = 0; e < 4; e++) {
                    __half h = __float2half_rn(f[e]);
                    Bs_h[(n4 + e) * LDT + k] = h;
                    Bs_l[(n4 + e) * LDT + k] = __float2half_rn(f[e] - __half2float(h));
                }
            }
        }
        __syncthreads();

#pragma unroll
        for (int ks = 0; ks < 2; ks++) {
            const int kk = ks * 16;
            wmma::fragment<wmma::matrix_a, 16, 16, 16, __half, wmma::row_major> ah[2], al[2];
#pragma unroll
            for (int i = 0; i < 2; i++) {
                wmma::load_matrix_sync(ah[i], As_h + (wm + i * 16) * LDT + kk, LDT);
                wmma::load_matrix_sync(al[i], As_l + (wm + i * 16) * LDT + kk, LDT);
            }
#pragma unroll
            for (int j = 0; j < 4; j++) {
                wmma::fragment<wmma::matrix_b, 16, 16, 16, __half, wmma::col_major> bh, bl;
                wmma::load_matrix_sync(bh, Bs_h + (wn + j * 16) * LDT + kk, LDT);
                wmma::load_matrix_sync(bl, Bs_l + (wn + j * 16) * LDT + kk, LDT);
#pragma unroll
                for (int i = 0; i < 2; i++) {
                    wmma::mma_sync(acc[i][j], ah[i], bh, acc[i][j]);
                    wmma::mma_sync(acc[i][j], ah[i], bl, acc[i][j]);
                    wmma::mma_sync(acc[i][j], al[i], bh, acc[i][j]);
                }
            }
        }
        __syncthreads();
    }

    if (alpha != 1.f) {
#pragma unroll
        for (int i = 0; i < 2; i++)
#pragma unroll
            for (int j = 0; j < 4; j++)
                for (int e = 0; e < acc[i][j].num_elements; e++)
                    acc[i][j].x[e] *= alpha;
    }
#pragma unroll
    for (int i = 0; i < 2; i++)
#pragma unroll
        for (int j = 0; j < 4; j++)
            wmma::store_matrix_sync(Cg + (long long)(wm + i * 16) * ldc + wn + j * 16,
                                    acc[i][j], ldc, wmma::mem_row_major);
}

// =========================== elementwise kernels ===========================
// row L2-normalize (in place) + copy to Xc + quality stat. 4096 rows, 256 thr.
__global__ void l2rowk(float* __restrict__ X, float* __restrict__ Xc,
                       float* __restrict__ qual, int mode)
{
    const int row = blockIdx.x, t = threadIdx.x;
    float* xr = X + (long long)row * 1024;
    float4 v = ((float4*)xr)[t];
    float ss = v.x*v.x + v.y*v.y + v.z*v.z + v.w*v.w;
    __shared__ float smA[8], smB[8], smC[8];
#pragma unroll
    for (int o = 16; o; o >>= 1) ss += __shfl_xor_sync(~0u, ss, o);
    if (!(t & 31)) smA[t >> 5] = ss;
    __syncthreads();
    ss = smA[0]+smA[1]+smA[2]+smA[3]+smA[4]+smA[5]+smA[6]+smA[7];
    const float inv = 1.f / fmaxf(sqrtf(ss), 1e-12f);
    v.x *= inv; v.y *= inv; v.z *= inv; v.w *= inv;
    ((float4*)xr)[t] = v;
    ((float4*)(Xc + (long long)row * 1024))[t] = v;
    float s1, s2 = 0.f;
    if (mode == 0) {
        s1 = v.x + v.y + v.z + v.w;
        s2 = v.x*v.x + v.y*v.y + v.z*v.z + v.w*v.w;
    } else {
        s1 = (v.x == 0.f) + (v.y == 0.f) + (v.z == 0.f) + (v.w == 0.f);
    }
#pragma unroll
    for (int o = 16; o; o >>= 1) {
        s1 += __shfl_xor_sync(~0u, s1, o);
        s2 += __shfl_xor_sync(~0u, s2, o);
    }
    if (!(t & 31)) { smB[t >> 5] = s1; smC[t >> 5] = s2; }
    __syncthreads();
    if (t == 0) {
        float a = smB[0]+smB[1]+smB[2]+smB[3]+smB[4]+smB[5]+smB[6]+smB[7];
        float b = smC[0]+smC[1]+smC[2]+smC[3]+smC[4]+smC[5]+smC[6]+smC[7];
        qual[row] = (mode == 0) ? (b - a * a * (1.f/1024.f)) * (1.f/1023.f)
                                : a * (1.f/1024.f);
    }
}

__global__ void softmaxk(float* __restrict__ S)
{
    float* row = S + (long long)blockIdx.x * 128;
    const int t = threadIdx.x, lane = t & 31, w = t >> 5;
    __shared__ float sh[4];
    float v = row[t];
    float m = v;
#pragma unroll
    for (int o = 16; o; o >>= 1) m = fmaxf(m, __shfl_xor_sync(~0u, m, o));
    if (!lane) sh[w] = m;
    __syncthreads();
    m = fmaxf(fmaxf(sh[0], sh[1]), fmaxf(sh[2], sh[3]));
    float e = expf(v - m);
    float s = e;
#pragma unroll
    for (int o = 16; o; o >>= 1) s += __shfl_xor_sync(~0u, s, o);
    __syncthreads();
    if (!lane) sh[w] = s;
    __syncthreads();
    s = sh[0] + sh[1] + sh[2] + sh[3];
    row[t] = e / s;
}

// pooled mean over p: grid (4, 8, 3), block 128
__global__ void poolk(const float* __restrict__ crt, const float* __restrict__ cdt,
                      const float* __restrict__ clt, float* __restrict__ pool)
{
    const int b = blockIdx.x, m = blockIdx.z;
    const int c = blockIdx.y * 128 + threadIdx.x;
    const float* src = (m == 0 ? crt : m == 1 ? cdt : clt) + (long long)b * 1048576 + c;
    float s = 0.f;
    for (int p = 0; p < 1024; p++) s += src[(long long)p * 1024];
    pool[(m * 4 + b) * 1024 + c] = s * (1.f / 1024.f);
}

__global__ void se1k(const float* __restrict__ w1, const float* __restrict__ b1,
                     const float* __restrict__ pool, float* __restrict__ hid)
{
    const int b = blockIdx.x, m = blockIdx.y, o = threadIdx.x;
    const float4* w = (const float4*)(w1 + ((long long)m * 64 + o) * 1024);
    const float4* p = (const float4*)(pool + (m * 4 + b) * 1024);
    float s = b1[m * 64 + o];
    for (int c = 0; c < 256; c++) {
        float4 a = w[c], q = p[c];
        s += a.x * q.x + a.y * q.y + a.z * q.z + a.w * q.w;
    }
    hid[(m * 4 + b) * 64 + o] = fmaxf(s, 0.f);
}

__global__ void se2k(const float* __restrict__ w2, const float* __restrict__ b2,
                     const float* __restrict__ hid, float* __restrict__ seg)
{
    const int b = blockIdx.x, m = blockIdx.y;
    const float4* h4 = (const float4*)(hid + (m * 4 + b) * 64);
    for (int o = threadIdx.x; o < 1024; o += 256) {
        const float4* w = (const float4*)(w2 + ((long long)m * 1024 + o) * 64);
        float s = b2[m * 1024 + o];
#pragma unroll
        for (int c = 0; c < 16; c++) {
            float4 a = w[c], q = h4[c];
            s += a.x * q.x + a.y * q.y + a.z * q.z + a.w * q.w;
        }
        seg[(m * 4 + b) * 1024 + o] = 1.f / (1.f + expf(-s));
    }
}

// crt[b][p][c] *= seg per-channel. i over 1M float4.
__global__ void sescalek(float4* __restrict__ cr, float4* __restrict__ cd,
                         float4* __restrict__ cl, const float* __restrict__ seg)
{
    const int i = blockIdx.x * 256 + threadIdx.x;
    const int b = i >> 18, c4 = i & 255;
    const float4* s4 = (const float4*)seg;
    float4 v, g;
    g = s4[b * 256 + c4];
    v = cr[i]; v.x*=g.x; v.y*=g.y; v.z*=g.z; v.w*=g.w; cr[i] = v;
    g = s4[(4 + b) * 256 + c4];
    v = cd[i]; v.x*=g.x; v.y*=g.y; v.z*=g.z; v.w*=g.w; cd[i] = v;
    g = s4[(8 + b) * 256 + c4];
    v = cl[i]; v.x*=g.x; v.y*=g.y; v.z*=g.z; v.w*=g.w; cl[i] = v;
}

// gates: grid 4096 (b*1024+p), block 128
__global__ void gatek(const float* __restrict__ crt, const float* __restrict__ cdt,
                      const float* __restrict__ clt, const float* __restrict__ gw,
                      const float* __restrict__ gb, const float* __restrict__ qual,
                      float* __restrict__ gates)
{
    const int row = blockIdx.x, b = row >> 10, p = row & 1023, t = threadIdx.x;
    const float* mods[3] = { crt, cdt, clt };
    float a0 = 0.f, a1 = 0.f, a2 = 0.f;
#pragma unroll
    for (int m = 0; m < 3; m++) {
        const float* r = mods[m] + (long long)b * 1048576 + (long long)p * 1024;
        const float* w = gw + m * 1024;
        for (int c = t; c < 1024; c += 128) {
            float v = r[c];
            a0 += w[c] * v; a1 += w[3075 + c] * v; a2 += w[6150 + c] * v;
        }
    }
    __shared__ float red[3][128];
    red[0][t] = a0; red[1][t] = a1; red[2][t] = a2;
    __syncthreads();
    for (int s = 64; s > 0; s >>= 1) {
        if (t < s) {
            red[0][t] += red[0][t+s]; red[1][t] += red[1][t+s]; red[2][t] += red[2][t+s];
        }
        __syncthreads();
    }
    if (t < 3) {
        float s = red[t][0];
        const float* wj = gw + t * 3075;
        s += wj[3072] * qual[row] + wj[3073] * qual[4096 + row]
           + wj[3074] * qual[8192 + row] + gb[t];
        gates[(b * 3 + t) * 1024 + p] = 1.f / (1.f + expf(-s));
    }
}

// ft[b][p][m*1024+c] = ref_m[b][p][c] * gates[b][m][p]. 3145728 float4.
__global__ void fusedk(const float4* __restrict__ cr, const float4* __restrict__ cd,
                       const float4* __restrict__ cl, const float* __restrict__ gates,
                       float4* __restrict__ fused)
{
    const int i = blockIdx.x * 256 + threadIdx.x;
    const int b = i / 786432;
    const int rem = i - b * 786432;
    const int p = rem / 768;
    const int q = rem - p * 768;
    const int m = q >> 8, c4 = q & 255;
    const float4* src = (m == 0 ? cr : m == 1 ? cd : cl);
    float4 v = src[b * 262144 + p * 256 + c4];
    const float g = gates[(b * 3 + m) * 1024 + p];
    v.x *= g; v.y *= g; v.z *= g; v.w *= g;
    fused[i] = v;
}

// =============================== host ======================================
extern "C" void kernel_launch(void* const* d_in, const int* in_sizes, int n_in,
                              void* d_out, int out_size)
{
    const float* rgb   = (const float*)d_in[0];
    const float* depth = (const float*)d_in[1];
    const float* lidar = (const float*)d_in[2];
    const float* prw = (const float*)d_in[3];   const float* prb = (const float*)d_in[4];
    const float* pdw = (const float*)d_in[5];   const float* pdb = (const float*)d_in[6];
    const float* plw = (const float*)d_in[7];   const float* plb = (const float*)d_in[8];
    const float* aqw = (const float*)d_in[9];   const float* aqb = (const float*)d_in[10];
    const float* akw = (const float*)d_in[11];  const float* akb = (const float*)d_in[12];
    const float* avw = (const float*)d_in[13];  const float* avb = (const float*)d_in[14];
    const float* aow = (const float*)d_in[15];  const float* aob = (const float*)d_in[16];
    const float* sw1 = (const float*)d_in[17];  const float* sb1 = (const float*)d_in[18];
    const float* sw2 = (const float*)d_in[19];  const float* sb2 = (const float*)d_in[20];
    const float* gw  = (const float*)d_in[21];  const float* gb  = (const float*)d_in[22];
    const float* fw  = (const float*)d_in[23];  const float* fb  = (const float*)d_in[24];
    float* out = (float*)d_out;

    float *rt, *dtt, *ltt, *crt, *cdt, *clt;
    float *Qb, *Kb, *Vb, *S, *AVt, *ft, *pool, *hid, *seg, *qual, *gates;
    cudaGetSymbolAddress((void**)&rt,   g_rt);
    cudaGetSymbolAddress((void**)&dtt,  g_dtt);
    cudaGetSymbolAddress((void**)&ltt,  g_ltt);
    cudaGetSymbolAddress((void**)&crt,  g_crt);
    cudaGetSymbolAddress((void**)&cdt,  g_cdt);
    cudaGetSymbolAddress((void**)&clt,  g_clt);
    cudaGetSymbolAddress((void**)&Qb,   g_Qb);
    cudaGetSymbolAddress((void**)&Kb,   g_Kb);
    cudaGetSymbolAddress((void**)&Vb,   g_Vb);
    cudaGetSymbolAddress((void**)&S,    g_Sb);
    cudaGetSymbolAddress((void**)&AVt,  g_AVt);
    cudaGetSymbolAddress((void**)&ft,   g_ft);
    cudaGetSymbolAddress((void**)&pool, g_pool);
    cudaGetSymbolAddress((void**)&hid,  g_hid);
    cudaGetSymbolAddress((void**)&seg,  g_seg);
    cudaGetSymbolAddress((void**)&qual, g_qual);
    cudaGetSymbolAddress((void**)&gates,g_gates);

    const long long M1 = 1048576LL;
    const float scale = 0.08838834764831845f;   // 128^-0.5

    // ---- projections: C[p][cout] = in^T * W^T + b  (A col-major from input)
    tcwmma<<<dim3(8, 8, 4), 256>>>(rgb, 1024, 524288, 0, 1, 1,
        prw, 512, 0, 0, 1, 0, rt, 1024, M1, 0, 1, prb, 1.f, 0, 512);
    tcwmma<<<dim3(8, 8, 4), 256>>>(depth, 1024, 262144, 0, 1, 1,
        pdw, 256, 0, 0, 1, 0, dtt, 1024, M1, 0, 1, pdb, 1.f, 0, 256);
    tcwmma<<<dim3(8, 8, 4), 256>>>(lidar, 1024, 65536, 0, 1, 1,
        plw, 64, 0, 0, 1, 0, ltt, 1024, M1, 0, 1, plb, 1.f, 0, 64);

    l2rowk<<<4096, 256>>>(rt,  crt, qual,        0);
    l2rowk<<<4096, 256>>>(dtt, cdt, qual + 4096, 1);
    l2rowk<<<4096, 256>>>(ltt, clt, qual + 8192, 1);

    // ---- six cross-attention blocks ----
    const float* qsrc[6]  = { rt, rt, dtt, dtt, ltt, ltt };
    const float* kvsrc[6] = { dtt, ltt, rt, ltt, rt, dtt };
    float*       accb[6]  = { crt, crt, cdt, cdt, clt, clt };
    for (int i = 0; i < 6; i++) {
        const long long wo = (long long)i * M1;
        // Q/K/V convs: A = features [p][c], B = W [cout][cin] -> C [p][cout]
        tcwmma<<<dim3(8, 8, 4), 256>>>(qsrc[i], 1024, M1, 0, 1, 0,
            aqw + wo, 1024, 0, 0, 1, 0, Qb, 1024, M1, 0, 1, aqb + i*1024, 1.f, 0, 1024);
        tcwmma<<<dim3(8, 8, 4), 256>>>(kvsrc[i], 1024, M1, 0, 1, 0,
            akw + wo, 1024, 0, 0, 1, 0, Kb, 1024, M1, 0, 1, akb + i*1024, 1.f, 0, 1024);
        tcwmma<<<dim3(8, 8, 4), 256>>>(kvsrc[i], 1024, M1, 0, 1, 0,
            avw + wo, 1024, 0, 0, 1, 0, Vb, 1024, M1, 0, 1, avb + i*1024, 1.f, 0, 1024);
        // scores: per z=(b*8+h): S_z[i][j] = scale * sum_p Q[p][h*128+i]*K[p][h*128+j]
        tcwmma<<<dim3(1, 1, 32), 256>>>(Qb, 1024, M1, 128, 8, 1,
            Kb, 1024, M1, 128, 8, 1, S, 128, 16384, 0, 1,
            (const float*)0, scale, 0, 1024);
        softmaxk<<<4096, 128>>>(S);
        // AV: AVt[p][h*128+i] = sum_j Vb[p][h*128+j] * S_z[i][j]
        tcwmma<<<dim3(1, 8, 32), 256>>>(Vb, 1024, M1, 128, 8, 0,
            S, 128, 16384, 0, 1, 0, AVt, 1024, M1, 128, 8,
            (const float*)0, 1.f, 0, 128);
        // O conv, accumulate into residual
        tcwmma<<<dim3(8, 8, 4), 256>>>(AVt, 1024, M1, 0, 1, 0,
            aow + wo, 1024, 0, 0, 1, 0, accb[i], 1024, M1, 0, 1,
            aob + i*1024, 1.f, 1, 1024);
    }

    // ---- SE gating ----
    poolk<<<dim3(4, 8, 3), 128>>>(crt, cdt, clt, pool);
    se1k<<<dim3(4, 3), 64>>>(sw1, sb1, pool, hid);
    se2k<<<dim3(4, 3), 256>>>(sw2, sb2, hid, seg);
    sescalek<<<4096, 256>>>((float4*)crt, (float4*)cdt, (float4*)clt, seg);

    // ---- adaptive gates + gated concat ----
    gatek<<<4096, 128>>>(crt, cdt, clt, gw, gb, qual, gates);
    fusedk<<<12288, 256>>>((const float4*)crt, (const float4*)cdt, (const float4*)clt,
                           gates, (float4*)ft);

    // ---- fusion: out[b][cout][p] = fw[cout][:] . ft[b][p][:] + fb ----
    tcwmma<<<dim3(8, 24, 4), 256>>>(fw, 3072, 0, 0, 1, 0,
        ft, 3072, 3145728, 0, 1, 0, out, 1024, 3145728, 0, 1, fb, 1.f, 2, 3072);
}

// round 14
// speedup vs baseline: 1.8893x; 1.5505x over previous
#include <cuda_runtime.h>
#include <cuda_fp16.h>
#include <mma.h>
#include <cstdint>
#include <math.h>

using namespace nvcuda;

// ============================ fp32 scratch =================================
__device__ float g_rt  [4194304];
__device__ float g_dtt [4194304];
__device__ float g_ltt [4194304];
__device__ float g_crt [4194304];
__device__ float g_cdt [4194304];
__device__ float g_clt [4194304];
__device__ float g_S   [524288];
__device__ float g_pool[12288];
__device__ float g_hid [768];
__device__ float g_seg [12288];
__device__ float g_qual[12288];
__device__ float g_gates[12288];

// ============================ fp16 hi/lo scratch ===========================
__device__ __half g_rgbtH[2097152], g_rgbtL[2097152];
__device__ __half g_dptH [1048576], g_dptL [1048576];
__device__ __half g_ldtH [262144],  g_ldtL [262144];
__device__ __half g_prwH [524288],  g_prwL [524288];
__device__ __half g_pdwH [262144],  g_pdwL [262144];
__device__ __half g_plwH [65536],   g_plwL [65536];
__device__ __half g_aqwH [6291456], g_aqwL [6291456];
__device__ __half g_akwH [6291456], g_akwL [6291456];
__device__ __half g_avwH [6291456], g_avwL [6291456];
__device__ __half g_aowH [6291456], g_aowL [6291456];
__device__ __half g_fwH  [9437184], g_fwL  [9437184];
__device__ __half g_rtH  [4194304], g_rtL  [4194304];
__device__ __half g_dttH [4194304], g_dttL [4194304];
__device__ __half g_lttH [4194304], g_lttL [4194304];
__device__ __half g_QTH  [4194304], g_QTL  [4194304];
__device__ __half g_KTH  [4194304], g_KTL  [4194304];
__device__ __half g_VbH  [4194304], g_VbL  [4194304];
__device__ __half g_SH   [524288],  g_SL   [524288];
__device__ __half g_AVtH [4194304], g_AVtL [4194304];
__device__ __half g_ftH  [12582912],g_ftL  [12582912];

// ============================ helpers ======================================
__device__ __forceinline__ uint32_t smem_u32(const void* p) {
    uint32_t a;
    asm("{ .reg .u64 t; cvta.to.shared.u64 t, %1; cvt.u32.u64 %0, t; }"
        : "=r"(a) : "l"(p));
    return a;
}
#define CP_ASYNC(dst, src) \
    asm volatile("cp.async.cg.shared.global [%0], [%1], 16;\n" :: "r"(dst), "l"(src))
#define CP_COMMIT() asm volatile("cp.async.commit_group;\n" ::)
#define CP_WAIT(n)  asm volatile("cp.async.wait_group %0;\n" :: "n"(n))

__device__ __forceinline__ void split2(float x, float y, __half2& h, __half2& l) {
    h = __floats2half2_rn(x, y);
    float2 f = __half22float2(h);
    l = __floats2half2_rn(x - f.x, y - f.y);
}

// ==================== fp16-split WMMA GEMM (all non-trans) =================
// C(m,n) = alpha * sum_k A(m,k)*B(n,k)  [+bias] [+C_old if flags&1]
// A tiles: Ah/Al [m][k] row-major (lda), B tiles: Bh/Bl [n][k] row-major (ldb).
// z offsets: (z/div)*so + (z%div)*si.
// mode 0: fp32 out C [m][n] (ldc). mode 1: half pairs OH/OL [m][n].
// mode 2: half pairs transposed [n][m] (ldc = out leading dim).
// flags: bit0 accumulate (mode 0 only), bit1 bias per m (else per n).
static const int LDT = 40;
static const int TILE_H = 128 * LDT;                 // halves per tile
static const int GSMEM = 2 * 4 * TILE_H * 2;         // 81920 bytes

__global__ __launch_bounds__(256, 2) void tcg(
    const __half* __restrict__ Ah, const __half* __restrict__ Al,
    int lda, long long sAo, long long sAi, int adiv,
    const __half* __restrict__ Bh, const __half* __restrict__ Bl,
    int ldb, long long sBo, long long sBi, int bdiv,
    float* __restrict__ C, __half* __restrict__ OH, __half* __restrict__ OL,
    int ldc, long long sCo, long long sCi, int cdiv,
    const float* __restrict__ bias, float alpha, int flags, int K, int mode)
{
    extern __shared__ __half smh[];
    const int tid = threadIdx.x, wid = tid >> 5, lane = tid & 31;
    const int z = blockIdx.z, m0 = blockIdx.y << 7, n0 = blockIdx.x << 7;
    const int wm = (wid >> 1) * 32, wn = (wid & 1) * 64;

    const long long aoff = (long long)(z / adiv) * sAo + (long long)(z % adiv) * sAi;
    const long long boff = (long long)(z / bdiv) * sBo + (long long)(z % bdiv) * sBi;
    const long long zoff = (long long)(z / cdiv) * sCo + (long long)(z % cdiv) * sCi;
    const __half* Agh = Ah + aoff + (long long)m0 * lda;
    const __half* Agl = Al + aoff + (long long)m0 * lda;
    const __half* Bgh = Bh + boff + (long long)n0 * ldb;
    const __half* Bgl = Bl + boff + (long long)n0 * ldb;
    float* Cg = (mode == 0) ? (C + zoff + (long long)m0 * ldc + n0) : (float*)0;

    wmma::fragment<wmma::accumulator, 16, 16, 16, float> acc[2][4];
#pragma unroll
    for (int i = 0; i < 2; i++)
#pragma unroll
        for (int j = 0; j < 4; j++) {
            if (flags & 1)
                wmma::load_matrix_sync(acc[i][j],
                    Cg + (long long)(wm + i * 16) * ldc + wn + j * 16, ldc,
                    wmma::mem_row_major);
            else
                wmma::fill_fragment(acc[i][j], 0.f);
        }

    // ---- bias as exact rank-1 MMA (cols 0/1 = hi/lo) in smem buf0 ----
    if (bias) {
        __half* As = smh;
        __half* Bs = smh + 2 * TILE_H;
        if (tid < 128) {
            const int r = tid;
#pragma unroll
            for (int c = 0; c < 16; c++) {
                As[r * LDT + c] = __float2half_rn(0.f);
                Bs[r * LDT + c] = __float2half_rn(0.f);
            }
            const __half one = __float2half_rn(1.f);
            if (flags & 2) {
                float bv = bias[m0 + r];
                __half bh = __float2half_rn(bv);
                As[r * LDT + 0] = bh;
                As[r * LDT + 1] = __float2half_rn(bv - __half2float(bh));
                Bs[r * LDT + 0] = one;  Bs[r * LDT + 1] = one;
            } else {
                float bv = bias[n0 + r];
                __half bh = __float2half_rn(bv);
                Bs[r * LDT + 0] = bh;
                Bs[r * LDT + 1] = __float2half_rn(bv - __half2float(bh));
                As[r * LDT + 0] = one;  As[r * LDT + 1] = one;
            }
        }
        __syncthreads();
        wmma::fragment<wmma::matrix_a, 16, 16, 16, __half, wmma::row_major> af;
        wmma::fragment<wmma::matrix_b, 16, 16, 16, __half, wmma::col_major> bf;
#pragma unroll
        for (int i = 0; i < 2; i++) {
            wmma::load_matrix_sync(af, As + (wm + i * 16) * LDT, LDT);
#pragma unroll
            for (int j = 0; j < 4; j++) {
                wmma::load_matrix_sync(bf, Bs + (wn + j * 16) * LDT, LDT);
                wmma::mma_sync(acc[i][j], af, bf, acc[i][j]);
            }
        }
        __syncthreads();
    }

    const uint32_t sbase = smem_u32(smh);
    const __half* srcs[4] = { Agh, Agl, Bgh, Bgl };
    const int lds[4] = { lda, lda, ldb, ldb };

    auto issue = [&](int buf, int k0) {
        const uint32_t bb = sbase + buf * 4 * TILE_H * 2;
#pragma unroll
        for (int t = 0; t < 4; t++) {
#pragma unroll
            for (int e = 0; e < 2; e++) {
                const int idx = tid * 2 + e;           // 0..511
                const int r = idx >> 2, q = idx & 3;
                const __half* src = srcs[t] + (long long)r * lds[t] + k0 + q * 8;
                const uint32_t dst = bb + t * TILE_H * 2 + (r * LDT + q * 8) * 2;
                CP_ASYNC(dst, src);
            }
        }
        CP_COMMIT();
    };

    const int nc = K >> 5;
    issue(0, 0);
    for (int c = 0; c < nc; c++) {
        if (c + 1 < nc) { issue((c + 1) & 1, (c + 1) << 5); CP_WAIT(1); }
        else           { CP_WAIT(0); }
        __syncthreads();
        const __half* bufb = smh + (c & 1) * 4 * TILE_H;
        const __half* Ash = bufb;
        const __half* Asl = bufb + TILE_H;
        const __half* Bsh = bufb + 2 * TILE_H;
        const __half* Bsl = bufb + 3 * TILE_H;
#pragma unroll
        for (int ks = 0; ks < 2; ks++) {
            const int kk = ks * 16;
            wmma::fragment<wmma::matrix_a, 16, 16, 16, __half, wmma::row_major> ah[2], al[2];
#pragma unroll
            for (int i = 0; i < 2; i++) {
                wmma::load_matrix_sync(ah[i], Ash + (wm + i * 16) * LDT + kk, LDT);
                wmma::load_matrix_sync(al[i], Asl + (wm + i * 16) * LDT + kk, LDT);
            }
#pragma unroll
            for (int j = 0; j < 4; j++) {
                wmma::fragment<wmma::matrix_b, 16, 16, 16, __half, wmma::col_major> bh, bl;
                wmma::load_matrix_sync(bh, Bsh + (wn + j * 16) * LDT + kk, LDT);
                wmma::load_matrix_sync(bl, Bsl + (wn + j * 16) * LDT + kk, LDT);
#pragma unroll
                for (int i = 0; i < 2; i++) {
                    wmma::mma_sync(acc[i][j], ah[i], bh, acc[i][j]);
                    wmma::mma_sync(acc[i][j], ah[i], bl, acc[i][j]);
                    wmma::mma_sync(acc[i][j], al[i], bh, acc[i][j]);
                }
            }
        }
        __syncthreads();
    }

    if (alpha != 1.f) {
#pragma unroll
        for (int i = 0; i < 2; i++)
#pragma unroll
            for (int j = 0; j < 4; j++)
                for (int e = 0; e < acc[i][j].num_elements; e++)
                    acc[i][j].x[e] *= alpha;
    }

    if (mode == 0) {
#pragma unroll
        for (int i = 0; i < 2; i++)
#pragma unroll
            for (int j = 0; j < 4; j++)
                wmma::store_matrix_sync(Cg + (long long)(wm + i * 16) * ldc + wn + j * 16,
                                        acc[i][j], ldc, wmma::mem_row_major);
    } else {
        // stage fp32 through smem (ld 68 vs 32-bank conflicts), emit half pairs
        float* stg = reinterpret_cast<float*>(smh) + wid * (32 * 68);
#pragma unroll
        for (int i = 0; i < 2; i++)
#pragma unroll
            for (int j = 0; j < 4; j++)
                wmma::store_matrix_sync(stg + i * 16 * 68 + j * 16, acc[i][j], 68,
                                        wmma::mem_row_major);
        __syncwarp();
        if (mode == 1) {            // out [m][n]
            const int gr = m0 + wm + lane;
            __half* oh = OH + zoff + (long long)gr * ldc + n0 + wn;
            __half* ol = OL + zoff + (long long)gr * ldc + n0 + wn;
#pragma unroll
            for (int cc = 0; cc < 64; cc += 2) {
                __half2 h, l;
                split2(stg[lane * 68 + cc], stg[lane * 68 + cc + 1], h, l);
                *(__half2*)(oh + cc) = h;
                *(__half2*)(ol + cc) = l;
            }
        } else {                    // mode 2: out [n][m]
#pragma unroll
            for (int e = 0; e < 2; e++) {
                const int cc = lane * 2 + e;
                __half* oh = OH + zoff + (long long)(n0 + wn + cc) * ldc + m0 + wm;
                __half* ol = OL + zoff + (long long)(n0 + wn + cc) * ldc + m0 + wm;
#pragma unroll
                for (int r = 0; r < 32; r += 2) {
                    __half2 h, l;
                    split2(stg[r * 68 + cc], stg[(r + 1) * 68 + cc], h, l);
                    *(__half2*)(oh + r) = h;
                    *(__half2*)(ol + r) = l;
                }
            }
        }
    }
}

// =========================== convert kernels ===============================
// fp32 -> half hi/lo, same layout. n4 = element count / 4.
__global__ void cvtwk(const float4* __restrict__ src, __half2* __restrict__ dH,
                      __half2* __restrict__ dL, int n4)
{
    const int i = blockIdx.x * 256 + threadIdx.x;
    if (i >= n4) return;
    float4 v = src[i];
    __half2 h0, l0, h1, l1;
    split2(v.x, v.y, h0, l0);
    split2(v.z, v.w, h1, l1);
    dH[2 * i] = h0; dH[2 * i + 1] = h1;
    dL[2 * i] = l0; dL[2 * i + 1] = l1;
}

// fp32 [z][R][C] -> half hi/lo [z][C][R]
__global__ void cvttk(const float* __restrict__ src, __half* __restrict__ dH,
                      __half* __restrict__ dL, int R, int C)
{
    __shared__ float t[32][33];
    const int r0 = blockIdx.y * 32, c0 = blockIdx.x * 32, z = blockIdx.z;
    const float* s = src + (long long)z * R * C;
    for (int rr = threadIdx.y; rr < 32; rr += 8)
        t[rr][threadIdx.x] = s[(long long)(r0 + rr) * C + c0 + threadIdx.x];
    __syncthreads();
    __half* oh = dH + (long long)z * R * C;
    __half* ol = dL + (long long)z * R * C;
    for (int rr = threadIdx.y; rr < 32; rr += 8) {
        float v = t[threadIdx.x][rr];
        __half h = __float2half_rn(v);
        oh[(long long)(c0 + rr) * R + r0 + threadIdx.x] = h;
        ol[(long long)(c0 + rr) * R + r0 + threadIdx.x] = __float2half_rn(v - __half2float(h));
    }
}

// =========================== elementwise kernels ===========================
// L2 norm row + write residual fp32 + half pairs + quality stat.
__global__ void l2rowk(const float* __restrict__ X, float* __restrict__ Xc,
                       __half2* __restrict__ XH, __half2* __restrict__ XL,
                       float* __restrict__ qual, int mode)
{
    const int row = blockIdx.x, t = threadIdx.x;
    const float* xr = X + (long long)row * 1024;
    float4 v = ((const float4*)xr)[t];
    float ss = v.x*v.x + v.y*v.y + v.z*v.z + v.w*v.w;
    __shared__ float smA[8], smB[8], smC[8];
#pragma unroll
    for (int o = 16; o; o >>= 1) ss += __shfl_xor_sync(~0u, ss, o);
    if (!(t & 31)) smA[t >> 5] = ss;
    __syncthreads();
    ss = smA[0]+smA[1]+smA[2]+smA[3]+smA[4]+smA[5]+smA[6]+smA[7];
    const float inv = 1.f / fmaxf(sqrtf(ss), 1e-12f);
    v.x *= inv; v.y *= inv; v.z *= inv; v.w *= inv;
    ((float4*)(Xc + (long long)row * 1024))[t] = v;
    __half2 h0, l0, h1, l1;
    split2(v.x, v.y, h0, l0);
    split2(v.z, v.w, h1, l1);
    const long long hb = (long long)row * 512 + t * 2;
    XH[hb] = h0; XH[hb + 1] = h1;
    XL[hb] = l0; XL[hb + 1] = l1;
    float s1, s2 = 0.f;
    if (mode == 0) {
        s1 = v.x + v.y + v.z + v.w;
        s2 = v.x*v.x + v.y*v.y + v.z*v.z + v.w*v.w;
    } else {
        s1 = (v.x == 0.f) + (v.y == 0.f) + (v.z == 0.f) + (v.w == 0.f);
    }
#pragma unroll
    for (int o = 16; o; o >>= 1) {
        s1 += __shfl_xor_sync(~0u, s1, o);
        s2 += __shfl_xor_sync(~0u, s2, o);
    }
    if (!(t & 31)) { smB[t >> 5] = s1; smC[t >> 5] = s2; }
    __syncthreads();
    if (t == 0) {
        float a = smB[0]+smB[1]+smB[2]+smB[3]+smB[4]+smB[5]+smB[6]+smB[7];
        float b = smC[0]+smC[1]+smC[2]+smC[3]+smC[4]+smC[5]+smC[6]+smC[7];
        qual[row] = (mode == 0) ? (b - a * a * (1.f/1024.f)) * (1.f/1023.f)
                                : a * (1.f/1024.f);
    }
}

// softmax over 128 + emit half pairs
__global__ void softmaxk(const float* __restrict__ S, __half* __restrict__ SH,
                         __half* __restrict__ SL)
{
    const float* row = S + (long long)blockIdx.x * 128;
    const int t = threadIdx.x, lane = t & 31, w = t >> 5;
    __shared__ float sh[4];
    float v = row[t];
    float m = v;
#pragma unroll
    for (int o = 16; o; o >>= 1) m = fmaxf(m, __shfl_xor_sync(~0u, m, o));
    if (!lane) sh[w] = m;
    __syncthreads();
    m = fmaxf(fmaxf(sh[0], sh[1]), fmaxf(sh[2], sh[3]));
    float e = expf(v - m);
    float s = e;
#pragma unroll
    for (int o = 16; o; o >>= 1) s += __shfl_xor_sync(~0u, s, o);
    __syncthreads();
    if (!lane) sh[w] = s;
    __syncthreads();
    s = sh[0] + sh[1] + sh[2] + sh[3];
    const float p = e / s;
    __half h = __float2half_rn(p);
    SH[(long long)blockIdx.x * 128 + t] = h;
    SL[(long long)blockIdx.x * 128 + t] = __float2half_rn(p - __half2float(h));
}

// pooled mean over p: grid (4, 8, 3), block 128
__global__ void poolk(const float* __restrict__ crt, const float* __restrict__ cdt,
                      const float* __restrict__ clt, float* __restrict__ pool)
{
    const int b = blockIdx.x, m = blockIdx.z;
    const int c = blockIdx.y * 128 + threadIdx.x;
    const float* src = (m == 0 ? crt : m == 1 ? cdt : clt) + (long long)b * 1048576 + c;
    float s = 0.f;
    for (int p = 0; p < 1024; p++) s += src[(long long)p * 1024];
    pool[(m * 4 + b) * 1024 + c] = s * (1.f / 1024.f);
}

__global__ void se1k(const float* __restrict__ w1, const float* __restrict__ b1,
                     const float* __restrict__ pool, float* __restrict__ hid)
{
    const int b = blockIdx.x, m = blockIdx.y, o = threadIdx.x;
    const float4* w = (const float4*)(w1 + ((long long)m * 64 + o) * 1024);
    const float4* p = (const float4*)(pool + (m * 4 + b) * 1024);
    float s = b1[m * 64 + o];
    for (int c = 0; c < 256; c++) {
        float4 a = w[c], q = p[c];
        s += a.x * q.x + a.y * q.y + a.z * q.z + a.w * q.w;
    }
    hid[(m * 4 + b) * 64 + o] = fmaxf(s, 0.f);
}

__global__ void se2k(const float* __restrict__ w2, const float* __restrict__ b2,
                     const float* __restrict__ hid, float* __restrict__ seg)
{
    const int b = blockIdx.x, m = blockIdx.y;
    const float4* h4 = (const float4*)(hid + (m * 4 + b) * 64);
    for (int o = threadIdx.x; o < 1024; o += 256) {
        const float4* w = (const float4*)(w2 + ((long long)m * 1024 + o) * 64);
        float s = b2[m * 1024 + o];
#pragma unroll
        for (int c = 0; c < 16; c++) {
            float4 a = w[c], q = h4[c];
            s += a.x * q.x + a.y * q.y + a.z * q.z + a.w * q.w;
        }
        seg[(m * 4 + b) * 1024 + o] = 1.f / (1.f + expf(-s));
    }
}

__global__ void sescalek(float4* __restrict__ cr, float4* __restrict__ cd,
                         float4* __restrict__ cl, const float* __restrict__ seg)
{
    const int i = blockIdx.x * 256 + threadIdx.x;
    const int b = i >> 18, c4 = i & 255;
    const float4* s4 = (const float4*)seg;
    float4 v, g;
    g = s4[b * 256 + c4];
    v = cr[i]; v.x*=g.x; v.y*=g.y; v.z*=g.z; v.w*=g.w; cr[i] = v;
    g = s4[(4 + b) * 256 + c4];
    v = cd[i]; v.x*=g.x; v.y*=g.y; v.z*=g.z; v.w*=g.w; cd[i] = v;
    g = s4[(8 + b) * 256 + c4];
    v = cl[i]; v.x*=g.x; v.y*=g.y; v.z*=g.z; v.w*=g.w; cl[i] = v;
}

__global__ void gatek(const float* __restrict__ crt, const float* __restrict__ cdt,
                      const float* __restrict__ clt, const float* __restrict__ gw,
                      const float* __restrict__ gb, const float* __restrict__ qual,
                      float* __restrict__ gates)
{
    const int row = blockIdx.x, b = row >> 10, p = row & 1023, t = threadIdx.x;
    const float* mods[3] = { crt, cdt, clt };
    float a0 = 0.f, a1 = 0.f, a2 = 0.f;
#pragma unroll
    for (int m = 0; m < 3; m++) {
        const float* r = mods[m] + (long long)b * 1048576 + (long long)p * 1024;
        const float* w = gw + m * 1024;
        for (int c = t; c < 1024; c += 128) {
            float v = r[c];
            a0 += w[c] * v; a1 += w[3075 + c] * v; a2 += w[6150 + c] * v;
        }
    }
    __shared__ float red[3][128];
    red[0][t] = a0; red[1][t] = a1; red[2][t] = a2;
    __syncthreads();
    for (int s = 64; s > 0; s >>= 1) {
        if (t < s) {
            red[0][t] += red[0][t+s]; red[1][t] += red[1][t+s]; red[2][t] += red[2][t+s];
        }
        __syncthreads();
    }
    if (t < 3) {
        float s = red[t][0];
        const float* wj = gw + t * 3075;
        s += wj[3072] * qual[row] + wj[3073] * qual[4096 + row]
           + wj[3074] * qual[8192 + row] + gb[t];
        gates[(b * 3 + t) * 1024 + p] = 1.f / (1.f + expf(-s));
    }
}

// ft half pairs [b][p][m*1024+c] = ref_m * gate. 3145728 float4 units.
__global__ void fusedk(const float4* __restrict__ cr, const float4* __restrict__ cd,
                       const float4* __restrict__ cl, const float* __restrict__ gates,
                       __half2* __restrict__ fH, __half2* __restrict__ fL)
{
    const int i = blockIdx.x * 256 + threadIdx.x;
    const int b = i / 786432;
    const int rem = i - b * 786432;
    const int p = rem / 768;
    const int q = rem - p * 768;
    const int m = q >> 8, c4 = q & 255;
    const float4* src = (m == 0 ? cr : m == 1 ? cd : cl);
    float4 v = src[b * 262144 + p * 256 + c4];
    const float g = gates[(b * 3 + m) * 1024 + p];
    v.x *= g; v.y *= g; v.z *= g; v.w *= g;
    __half2 h0, l0, h1, l1;
    split2(v.x, v.y, h0, l0);
    split2(v.z, v.w, h1, l1);
    fH[2 * i] = h0; fH[2 * i + 1] = h1;
    fL[2 * i] = l0; fL[2 * i + 1] = l1;
}

// =============================== host ======================================
#define GSA(v, s) cudaGetSymbolAddress((void**)&v, s)

extern "C" void kernel_launch(void* const* d_in, const int* in_sizes, int n_in,
                              void* d_out, int out_size)
{
    const float* rgb   = (const float*)d_in[0];
    const float* depth = (const float*)d_in[1];
    const float* lidar = (const float*)d_in[2];
    const float* prw = (const float*)d_in[3];   const float* prb = (const float*)d_in[4];
    const float* pdw = (const float*)d_in[5];   const float* pdb = (const float*)d_in[6];
    const float* plw = (const float*)d_in[7];   const float* plb = (const float*)d_in[8];
    const float* aqw = (const float*)d_in[9];   const float* aqb = (const float*)d_in[10];
    const float* akw = (const float*)d_in[11];  const float* akb = (const float*)d_in[12];
    const float* avw = (const float*)d_in[13];  const float* avb = (const float*)d_in[14];
    const float* aow = (const float*)d_in[15];  const float* aob = (const float*)d_in[16];
    const float* sw1 = (const float*)d_in[17];  const float* sb1 = (const float*)d_in[18];
    const float* sw2 = (const float*)d_in[19];  const float* sb2 = (const float*)d_in[20];
    const float* gw  = (const float*)d_in[21];  const float* gb  = (const float*)d_in[22];
    const float* fw  = (const float*)d_in[23];  const float* fb  = (const float*)d_in[24];
    float* out = (float*)d_out;

    float *rt, *dtt, *ltt, *crt, *cdt, *clt, *S;
    float *pool, *hid, *seg, *qual, *gates;
    GSA(rt, g_rt); GSA(dtt, g_dtt); GSA(ltt, g_ltt);
    GSA(crt, g_crt); GSA(cdt, g_cdt); GSA(clt, g_clt);
    GSA(S, g_S); GSA(pool, g_pool); GSA(hid, g_hid);
    GSA(seg, g_seg); GSA(qual, g_qual); GSA(gates, g_gates);

    __half *rgbtH,*rgbtL,*dptH,*dptL,*ldtH,*ldtL;
    __half *prwH,*prwL,*pdwH,*pdwL,*plwH,*plwL;
    __half *aqwH,*aqwL,*akwH,*akwL,*avwH,*avwL,*aowH,*aowL,*fwH,*fwL;
    __half *rtH,*rtL,*dttH,*dttL,*lttH,*lttL;
    __half *QTH,*QTL,*KTH,*KTL,*VbH,*VbL,*SH,*SL,*AVtH,*AVtL,*ftH,*ftL;
    GSA(rgbtH,g_rgbtH); GSA(rgbtL,g_rgbtL); GSA(dptH,g_dptH); GSA(dptL,g_dptL);
    GSA(ldtH,g_ldtH); GSA(ldtL,g_ldtL);
    GSA(prwH,g_prwH); GSA(prwL,g_prwL); GSA(pdwH,g_pdwH); GSA(pdwL,g_pdwL);
    GSA(plwH,g_plwH); GSA(plwL,g_plwL);
    GSA(aqwH,g_aqwH); GSA(aqwL,g_aqwL); GSA(akwH,g_akwH); GSA(akwL,g_akwL);
    GSA(avwH,g_avwH); GSA(avwL,g_avwL); GSA(aowH,g_aowH); GSA(aowL,g_aowL);
    GSA(fwH,g_fwH); GSA(fwL,g_fwL);
    GSA(rtH,g_rtH); GSA(rtL,g_rtL); GSA(dttH,g_dttH); GSA(dttL,g_dttL);
    GSA(lttH,g_lttH); GSA(lttL,g_lttL);
    GSA(QTH,g_QTH); GSA(QTL,g_QTL); GSA(KTH,g_KTH); GSA(KTL,g_KTL);
    GSA(VbH,g_VbH); GSA(VbL,g_VbL); GSA(SH,g_SH); GSA(SL,g_SL);
    GSA(AVtH,g_AVtH); GSA(AVtL,g_AVtL); GSA(ftH,g_ftH); GSA(ftL,g_ftL);

    cudaFuncSetAttribute(tcg, cudaFuncAttributeMaxDynamicSharedMemorySize, GSMEM);

    const long long M1 = 1048576LL;
    const float scale = 0.08838834764831845f;   // 128^-0.5
    __half* NH = (__half*)0;

    // ---- one-shot weight converts ----
    cvtwk<<<512, 256>>>((const float4*)prw, (__half2*)prwH, (__half2*)prwL, 131072);
    cvtwk<<<256, 256>>>((const float4*)pdw, (__half2*)pdwH, (__half2*)pdwL, 65536);
    cvtwk<<<64, 256>>>((const float4*)plw, (__half2*)plwH, (__half2*)plwL, 16384);
    cvtwk<<<6144, 256>>>((const float4*)aqw, (__half2*)aqwH, (__half2*)aqwL, 1572864);
    cvtwk<<<6144, 256>>>((const float4*)akw, (__half2*)akwH, (__half2*)akwL, 1572864);
    cvtwk<<<6144, 256>>>((const float4*)avw, (__half2*)avwH, (__half2*)avwL, 1572864);
    cvtwk<<<6144, 256>>>((const float4*)aow, (__half2*)aowH, (__half2*)aowL, 1572864);
    cvtwk<<<9216, 256>>>((const float4*)fw,  (__half2*)fwH,  (__half2*)fwL,  2359296);

    // ---- input transpose-converts: [b][cin][p] -> halves [b][p][cin] ----
    cvttk<<<dim3(32, 16, 4), dim3(32, 8)>>>(rgb,   rgbtH, rgbtL, 512, 1024);
    cvttk<<<dim3(32,  8, 4), dim3(32, 8)>>>(depth, dptH,  dptL,  256, 1024);
    cvttk<<<dim3(32,  2, 4), dim3(32, 8)>>>(lidar, ldtH,  ldtL,   64, 1024);

    // ---- projections (mode 0 fp32 out), then fused l2norm/halves/stat ----
    tcg<<<dim3(8, 8, 4), 256, GSMEM>>>(rgbtH, rgbtL, 512, 524288, 0, 1,
        prwH, prwL, 512, 0, 0, 1, rt, NH, NH, 1024, M1, 0, 1, prb, 1.f, 0, 512, 0);
    tcg<<<dim3(8, 8, 4), 256, GSMEM>>>(dptH, dptL, 256, 262144, 0, 1,
        pdwH, pdwL, 256, 0, 0, 1, dtt, NH, NH, 1024, M1, 0, 1, pdb, 1.f, 0, 256, 0);
    tcg<<<dim3(8, 8, 4), 256, GSMEM>>>(ldtH, ldtL, 64, 65536, 0, 1,
        plwH, plwL, 64, 0, 0, 1, ltt, NH, NH, 1024, M1, 0, 1, plb, 1.f, 0, 64, 0);

    l2rowk<<<4096, 256>>>(rt,  crt, (__half2*)rtH,  (__half2*)rtL,  qual,        0);
    l2rowk<<<4096, 256>>>(dtt, cdt, (__half2*)dttH, (__half2*)dttL, qual + 4096, 1);
    l2rowk<<<4096, 256>>>(ltt, clt, (__half2*)lttH, (__half2*)lttL, qual + 8192, 1);

    // ---- six cross-attention blocks ----
    const __half* qsH[6]  = { rtH, rtH, dttH, dttH, lttH, lttH };
    const __half* qsL[6]  = { rtL, rtL, dttL, dttL, lttL, lttL };
    const __half* kvH[6]  = { dttH, lttH, rtH, lttH, rtH, dttH };
    const __half* kvL[6]  = { dttL, lttL, rtL, lttL, rtL, dttL };
    float*        accb[6] = { crt, crt, cdt, cdt, clt, clt };
    const float*  qbias[6] = { aqb, aqb+1024, aqb+2048, aqb+3072, aqb+4096, aqb+5120 };
    for (int i = 0; i < 6; i++) {
        const long long wo = (long long)i * M1;
        // Q conv -> transposed halves QT [b][c][p]
        tcg<<<dim3(8, 8, 4), 256, GSMEM>>>(qsH[i], qsL[i], 1024, M1, 0, 1,
            aqwH + wo, aqwL + wo, 1024, 0, 0, 1, (float*)0, QTH, QTL,
            1024, M1, 0, 1, aqb + i*1024, 1.f, 0, 1024, 2);
        // K conv -> transposed halves KT
        tcg<<<dim3(8, 8, 4), 256, GSMEM>>>(kvH[i], kvL[i], 1024, M1, 0, 1,
            akwH + wo, akwL + wo, 1024, 0, 0, 1, (float*)0, KTH, KTL,
            1024, M1, 0, 1, akb + i*1024, 1.f, 0, 1024, 2);
        // V conv -> halves Vb [b][p][c]
        tcg<<<dim3(8, 8, 4), 256, GSMEM>>>(kvH[i], kvL[i], 1024, M1, 0, 1,
            avwH + wo, avwL + wo, 1024, 0, 0, 1, (float*)0, VbH, VbL,
            1024, M1, 0, 1, avb + i*1024, 1.f, 0, 1024, 1);
        // scores (fp32): S_z[i][j] = scale * sum_p QT[c_i][p] * KT[c_j][p]
        tcg<<<dim3(1, 1, 32), 256, GSMEM>>>(QTH, QTL, 1024, M1, 131072, 8,
            KTH, KTL, 1024, M1, 131072, 8, S, NH, NH,
            128, 16384, 0, 1, (const float*)0, scale, 0, 1024, 0);
        softmaxk<<<4096, 128>>>(S, SH, SL);
        // AV -> halves AVt [b][p][h*128+i]
        tcg<<<dim3(1, 8, 32), 256, GSMEM>>>(VbH, VbL, 1024, M1, 128, 8,
            SH, SL, 128, 16384, 0, 1, (float*)0, AVtH, AVtL,
            1024, M1, 128, 8, (const float*)0, 1.f, 0, 128, 1);
        // O conv, accumulate fp32 into residual
        tcg<<<dim3(8, 8, 4), 256, GSMEM>>>(AVtH, AVtL, 1024, M1, 0, 1,
            aowH + wo, aowL + wo, 1024, 0, 0, 1, accb[i], NH, NH,
            1024, M1, 0, 1, aob + i*1024, 1.f, 1, 1024, 0);
    }
    (void)qbias;

    // ---- SE gating ----
    poolk<<<dim3(4, 8, 3), 128>>>(crt, cdt, clt, pool);
    se1k<<<dim3(4, 3), 64>>>(sw1, sb1, pool, hid);
    se2k<<<dim3(4, 3), 256>>>(sw2, sb2, hid, seg);
    sescalek<<<4096, 256>>>((float4*)crt, (float4*)cdt, (float4*)clt, seg);

    // ---- adaptive gates + gated concat (emit half pairs) ----
    gatek<<<4096, 128>>>(crt, cdt, clt, gw, gb, qual, gates);
    fusedk<<<12288, 256>>>((const float4*)crt, (const float4*)cdt, (const float4*)clt,
                           gates, (__half2*)ftH, (__half2*)ftL);

    // ---- fusion: out[b][cout][p] = fw . ft[b][p][:] + fb (bias per m) ----
    tcg<<<dim3(8, 24, 4), 256, GSMEM>>>(fwH, fwL, 3072, 0, 0, 1,
        ftH, ftL, 3072, 3145728, 0, 1, out, NH, NH,
        1024, 3145728, 0, 1, fb, 1.f, 2, 3072, 0);
}